// round 2
// baseline (speedup 1.0000x reference)
#include <cuda_runtime.h>
#include <math.h>

#define B_SZ 16
#define C_SZ 512
#define L_SZ 1024
#define BN_EPS 1e-5f

#define CL (C_SZ * L_SZ)        // 524288
#define LL (L_SZ * L_SZ)        // 1048576

// ---------------- scratch (static device globals; no allocation) ----------------
__device__ float g_mean[C_SZ];
__device__ float g_rstd[C_SZ];
__device__ float g_hn[B_SZ * CL];
__device__ float g_q[B_SZ * CL];
__device__ float g_k[B_SZ * CL];
__device__ float g_v[B_SZ * CL];
__device__ float g_attn[B_SZ * LL];
__device__ float g_h[B_SZ * CL];

// ---------------- BatchNorm statistics: one block per channel ----------------
__global__ __launch_bounds__(256) void bn_stats(const float* __restrict__ x) {
    const int c = blockIdx.x;
    const float* xc = x + (size_t)c * L_SZ;
    float s = 0.f, ss = 0.f;
    for (int idx = threadIdx.x; idx < B_SZ * L_SZ; idx += 256) {
        int b = idx >> 10;
        int l = idx & (L_SZ - 1);
        float v = xc[(size_t)b * CL + l];
        s += v;
        ss += v * v;
    }
    __shared__ float sh_s[256], sh_ss[256];
    sh_s[threadIdx.x] = s;
    sh_ss[threadIdx.x] = ss;
    __syncthreads();
    for (int off = 128; off > 0; off >>= 1) {
        if (threadIdx.x < off) {
            sh_s[threadIdx.x] += sh_s[threadIdx.x + off];
            sh_ss[threadIdx.x] += sh_ss[threadIdx.x + off];
        }
        __syncthreads();
    }
    if (threadIdx.x == 0) {
        const float inv_n = 1.f / (float)(B_SZ * L_SZ);
        float m = sh_s[0] * inv_n;
        float var = sh_ss[0] * inv_n - m * m;
        g_mean[c] = m;
        g_rstd[c] = rsqrtf(var + BN_EPS);
    }
}

// ---------------- BatchNorm apply (vectorized) ----------------
__global__ __launch_bounds__(256) void bn_apply(const float* __restrict__ x,
                                                const float* __restrict__ gamma,
                                                const float* __restrict__ beta) {
    int i = blockIdx.x * 256 + threadIdx.x;           // float4 index
    const int n4 = B_SZ * CL / 4;
    if (i >= n4) return;
    int c = (i >> 8) & (C_SZ - 1);                    // (i*4 / L) % C, L=1024
    float sc = g_rstd[c] * gamma[c];
    float sh = beta[c] - g_mean[c] * sc;
    float4 xv = ((const float4*)x)[i];
    float4 o;
    o.x = xv.x * sc + sh;
    o.y = xv.y * sc + sh;
    o.z = xv.z * sc + sh;
    o.w = xv.w * sc + sh;
    ((float4*)g_hn)[i] = o;
}

// ---------------- Generic batched SGEMM ----------------
// C[m,n] = alpha * sum_k opA(m,k) * opB(k,n)  (+ bias[m]) (+ res[m,n])
// TA: A is [K x M] (lda over K-rows), else [M x K]
// TB: B is [N x K] (ldb over N-rows), else [K x N]
template <bool TA, bool TB, bool BIAS, bool RES>
__global__ __launch_bounds__(256) void gemm_kernel(
    const float* __restrict__ A, const float* __restrict__ Bm,
    const float* __restrict__ bias, const float* __restrict__ res,
    float* __restrict__ Cout,
    int K, int lda, int ldb, int ldc,
    long sA, long sB, long sC, long sRes, float alpha) {
    const int BK = 8;
    __shared__ float As[BK][128];
    __shared__ float Bs[BK][128];

    const int bz = blockIdx.z;
    A += (size_t)bz * sA;
    Bm += (size_t)bz * sB;
    Cout += (size_t)bz * sC;
    const float* resp = RES ? res + (size_t)bz * sRes : nullptr;

    const int bm = blockIdx.y * 128;
    const int bn = blockIdx.x * 128;
    const int tid = threadIdx.x;
    const int tx = tid & 15;   // 0..15  -> 8 cols each
    const int ty = tid >> 4;   // 0..15  -> 8 rows each

    float acc[8][8];
#pragma unroll
    for (int i = 0; i < 8; i++)
#pragma unroll
        for (int j = 0; j < 8; j++) acc[i][j] = 0.f;

    for (int k0 = 0; k0 < K; k0 += BK) {
        // ---- load A tile into As[k][m] ----
        if (!TA) {
            int r = tid >> 1;            // 0..127 (M)
            int q = (tid & 1) * 4;       // 0 or 4 (K)
            float4 v = *(const float4*)&A[(size_t)(bm + r) * lda + k0 + q];
            As[q + 0][r] = v.x;
            As[q + 1][r] = v.y;
            As[q + 2][r] = v.z;
            As[q + 3][r] = v.w;
        } else {
            int r = tid >> 5;            // 0..7 (K)
            int q = (tid & 31) * 4;      // 0..124 (M)
            float4 v = *(const float4*)&A[(size_t)(k0 + r) * lda + bm + q];
            *(float4*)&As[r][q] = v;
        }
        // ---- load B tile into Bs[k][n] ----
        if (!TB) {
            int r = tid >> 5;            // K
            int q = (tid & 31) * 4;      // N
            float4 v = *(const float4*)&Bm[(size_t)(k0 + r) * ldb + bn + q];
            *(float4*)&Bs[r][q] = v;
        } else {
            int r = tid >> 1;            // N
            int q = (tid & 1) * 4;       // K
            float4 v = *(const float4*)&Bm[(size_t)(bn + r) * ldb + k0 + q];
            Bs[q + 0][r] = v.x;
            Bs[q + 1][r] = v.y;
            Bs[q + 2][r] = v.z;
            Bs[q + 3][r] = v.w;
        }
        __syncthreads();

#pragma unroll
        for (int k = 0; k < BK; k++) {
            float ar[8], br[8];
#pragma unroll
            for (int i = 0; i < 8; i++) ar[i] = As[k][ty * 8 + i];
#pragma unroll
            for (int j = 0; j < 8; j++) br[j] = Bs[k][tx * 8 + j];
#pragma unroll
            for (int i = 0; i < 8; i++)
#pragma unroll
                for (int j = 0; j < 8; j++) acc[i][j] += ar[i] * br[j];
        }
        __syncthreads();
    }

    // ---- epilogue ----
#pragma unroll
    for (int i = 0; i < 8; i++) {
        int m = bm + ty * 8 + i;
        float bi = BIAS ? bias[m] : 0.f;
#pragma unroll
        for (int j = 0; j < 8; j += 4) {
            int n = bn + tx * 8 + j;
            float4 o;
            o.x = acc[i][j + 0] * alpha + bi;
            o.y = acc[i][j + 1] * alpha + bi;
            o.z = acc[i][j + 2] * alpha + bi;
            o.w = acc[i][j + 3] * alpha + bi;
            if (RES) {
                float4 rv = *(const float4*)&resp[(size_t)m * ldc + n];
                o.x += rv.x; o.y += rv.y; o.z += rv.z; o.w += rv.w;
            }
            *(float4*)&Cout[(size_t)m * ldc + n] = o;
        }
    }
}

// ---------------- row softmax (one block per row of 1024) ----------------
__global__ __launch_bounds__(256) void softmax_rows(float* __restrict__ attn) {
    const size_t row = blockIdx.x;
    float4* p4 = (float4*)(attn + row * L_SZ);
    const int t = threadIdx.x;
    float4 x = p4[t];

    __shared__ float sh[256];
    float m = fmaxf(fmaxf(x.x, x.y), fmaxf(x.z, x.w));
    sh[t] = m;
    __syncthreads();
    for (int o = 128; o > 0; o >>= 1) {
        if (t < o) sh[t] = fmaxf(sh[t], sh[t + o]);
        __syncthreads();
    }
    m = sh[0];
    __syncthreads();

    x.x = expf(x.x - m);
    x.y = expf(x.y - m);
    x.z = expf(x.z - m);
    x.w = expf(x.w - m);
    sh[t] = x.x + x.y + x.z + x.w;
    __syncthreads();
    for (int o = 128; o > 0; o >>= 1) {
        if (t < o) sh[t] += sh[t + o];
        __syncthreads();
    }
    float inv = 1.f / sh[0];
    x.x *= inv; x.y *= inv; x.z *= inv; x.w *= inv;
    p4[t] = x;
}

// ---------------- launch ----------------
extern "C" void kernel_launch(void* const* d_in, const int* in_sizes, int n_in,
                              void* d_out, int out_size) {
    const float* x     = (const float*)d_in[0];
    const float* gamma = (const float*)d_in[1];
    const float* beta  = (const float*)d_in[2];
    const float* Wq    = (const float*)d_in[3];
    const float* bq    = (const float*)d_in[4];
    const float* Wk    = (const float*)d_in[5];
    const float* bk    = (const float*)d_in[6];
    const float* Wv    = (const float*)d_in[7];
    const float* bv    = (const float*)d_in[8];
    const float* Wp    = (const float*)d_in[9];
    const float* bp    = (const float*)d_in[10];
    float* out = (float*)d_out;

    float *p_hn, *p_q, *p_k, *p_v, *p_attn, *p_h;
    cudaGetSymbolAddress((void**)&p_hn, g_hn);
    cudaGetSymbolAddress((void**)&p_q, g_q);
    cudaGetSymbolAddress((void**)&p_k, g_k);
    cudaGetSymbolAddress((void**)&p_v, g_v);
    cudaGetSymbolAddress((void**)&p_attn, g_attn);
    cudaGetSymbolAddress((void**)&p_h, g_h);

    // 1. BatchNorm statistics
    bn_stats<<<C_SZ, 256>>>(x);

    // 2. Normalize
    bn_apply<<<(B_SZ * CL / 4 + 255) / 256, 256>>>(x, gamma, beta);

    // 3. Q, K, V pointwise GEMMs: [C,C] x hn_b[C,L] + bias
    dim3 gp(L_SZ / 128, C_SZ / 128, B_SZ);   // (8,4,16)
    gemm_kernel<false, false, true, false><<<gp, 256>>>(
        Wq, p_hn, bq, nullptr, p_q, C_SZ, C_SZ, L_SZ, L_SZ, 0, CL, CL, 0, 1.f);
    gemm_kernel<false, false, true, false><<<gp, 256>>>(
        Wk, p_hn, bk, nullptr, p_k, C_SZ, C_SZ, L_SZ, L_SZ, 0, CL, CL, 0, 1.f);
    gemm_kernel<false, false, true, false><<<gp, 256>>>(
        Wv, p_hn, bv, nullptr, p_v, C_SZ, C_SZ, L_SZ, L_SZ, 0, CL, CL, 0, 1.f);

    // 4. Attention scores: attn[b,i,j] = sum_c q[b,c,i] k[b,c,j] * C^-0.5
    dim3 ga(L_SZ / 128, L_SZ / 128, B_SZ);   // (8,8,16)
    const float alpha = 1.f / sqrtf((float)C_SZ);
    gemm_kernel<true, false, false, false><<<ga, 256>>>(
        p_q, p_k, nullptr, nullptr, p_attn, C_SZ, L_SZ, L_SZ, L_SZ, CL, CL, LL, 0, alpha);

    // 5. Softmax over j
    softmax_rows<<<B_SZ * L_SZ, 256>>>(p_attn);

    // 6. h_[b,c,i] = sum_j v[b,c,j] attn[b,i,j]  (A = v [M=C,K=L], B = attn [N=L,K=L] transposed)
    dim3 gv(L_SZ / 128, C_SZ / 128, B_SZ);   // (8,4,16)
    gemm_kernel<false, true, false, false><<<gv, 256>>>(
        p_v, p_attn, nullptr, nullptr, p_h, L_SZ, L_SZ, L_SZ, L_SZ, CL, LL, CL, 0, 1.f);

    // 7. Projection + bias + residual -> d_out
    gemm_kernel<false, false, true, true><<<gp, 256>>>(
        Wp, p_h, bp, x, out, C_SZ, C_SZ, L_SZ, L_SZ, 0, CL, CL, CL, 1.f);
}

// round 7
// speedup vs baseline: 2.4374x; 2.4374x over previous
#include <cuda_runtime.h>
#include <cuda_bf16.h>
#include <cstdint>
#include <math.h>

#define B_SZ 16
#define C_SZ 512
#define L_SZ 1024
#define BN_EPS 1e-5f
#define CL (C_SZ * L_SZ)        // 524288
#define LL (L_SZ * L_SZ)        // 1048576

// ======================= scratch (static device globals) =======================
__device__ float g_mean[C_SZ];
__device__ float g_rstd[C_SZ];
__device__ __nv_bfloat16 g_xt_hi[B_SZ * CL];   // RAW x, transposed [B,L,C], split
__device__ __nv_bfloat16 g_xt_lo[B_SZ * CL];
__device__ __nv_bfloat16 g_w_hi[4 * C_SZ * C_SZ];  // Wq',Wk',Wv' (BN-folded), Wp (plain)
__device__ __nv_bfloat16 g_w_lo[4 * C_SZ * C_SZ];
__device__ float g_bfold[3 * C_SZ];            // folded biases for q,k,v only
__device__ __nv_bfloat16 g_qt_hi[B_SZ * CL];   // q transposed [B,L,C]
__device__ __nv_bfloat16 g_qt_lo[B_SZ * CL];
__device__ __nv_bfloat16 g_kt_hi[B_SZ * CL];
__device__ __nv_bfloat16 g_kt_lo[B_SZ * CL];
__device__ __nv_bfloat16 g_v_hi[B_SZ * CL];    // v natural [B,C,L]
__device__ __nv_bfloat16 g_v_lo[B_SZ * CL];
__device__ float g_scores[B_SZ * LL];
__device__ __nv_bfloat16 g_at_hi[B_SZ * LL];   // attn probs [B,L,L]
__device__ __nv_bfloat16 g_at_lo[B_SZ * LL];
__device__ __nv_bfloat16 g_ht_hi[B_SZ * CL];   // h_ transposed [B,L,C]
__device__ __nv_bfloat16 g_ht_lo[B_SZ * CL];

// ======================= helpers =======================
__device__ __forceinline__ uint32_t smem_to_u32(const void* p) {
    uint32_t a;
    asm("{ .reg .u64 t; cvta.to.shared.u64 t, %1; cvt.u32.u64 %0, t; }" : "=r"(a) : "l"(p));
    return a;
}
__device__ __forceinline__ void cp16(uint32_t dst, const void* src) {
    asm volatile("cp.async.cg.shared.global [%0], [%1], 16;" :: "r"(dst), "l"(src));
}
__device__ __forceinline__ void cp_commit() {
    asm volatile("cp.async.commit_group;");
}
template <int N>
__device__ __forceinline__ void cp_wait() {
    asm volatile("cp.async.wait_group %0;" :: "n"(N));
}
__device__ __forceinline__ uint32_t lds32(uint32_t addr) {
    uint32_t v;
    asm volatile("ld.shared.b32 %0, [%1];" : "=r"(v) : "r"(addr));
    return v;
}
__device__ __forceinline__ void mma16816(float* c, const uint32_t* a, uint32_t b0, uint32_t b1) {
    asm volatile(
        "mma.sync.aligned.m16n8k16.row.col.f32.bf16.bf16.f32 "
        "{%0,%1,%2,%3}, {%4,%5,%6,%7}, {%8,%9}, {%0,%1,%2,%3};"
        : "+f"(c[0]), "+f"(c[1]), "+f"(c[2]), "+f"(c[3])
        : "r"(a[0]), "r"(a[1]), "r"(a[2]), "r"(a[3]), "r"(b0), "r"(b1));
}
__device__ __forceinline__ void split_bf16(float v, __nv_bfloat16& h, __nv_bfloat16& l) {
    h = __float2bfloat16(v);
    l = __float2bfloat16(v - __bfloat162float(h));
}
__device__ __forceinline__ uint32_t pack_bf16(__nv_bfloat16 a, __nv_bfloat16 b) {
    return (uint32_t)__bfloat16_as_ushort(a) | ((uint32_t)__bfloat16_as_ushort(b) << 16);
}

// ======================= BatchNorm stats =======================
__global__ __launch_bounds__(256) void bn_stats(const float* __restrict__ x) {
    const int c = blockIdx.x;
    const float* xc = x + (size_t)c * L_SZ;
    float s = 0.f, ss = 0.f;
    for (int idx = threadIdx.x; idx < B_SZ * L_SZ; idx += 256) {
        int b = idx >> 10, l = idx & (L_SZ - 1);
        float v = xc[(size_t)b * CL + l];
        s += v; ss += v * v;
    }
    __shared__ float shs[256], shq[256];
    shs[threadIdx.x] = s; shq[threadIdx.x] = ss;
    __syncthreads();
    for (int o = 128; o > 0; o >>= 1) {
        if (threadIdx.x < o) { shs[threadIdx.x] += shs[threadIdx.x + o]; shq[threadIdx.x] += shq[threadIdx.x + o]; }
        __syncthreads();
    }
    if (threadIdx.x == 0) {
        const float inv_n = 1.f / (float)(B_SZ * L_SZ);
        float m = shs[0] * inv_n;
        float var = shq[0] * inv_n - m * m;
        g_mean[c] = m;
        g_rstd[c] = rsqrtf(var + BN_EPS);
    }
}

// ======================= x -> RAW transposed, bf16-split =======================
// NOTE: no normalization here. BN is folded into Wq/Wk/Wv + biases instead.
__global__ __launch_bounds__(256) void transpose_split(
    const float* __restrict__ x,
    __nv_bfloat16* __restrict__ th, __nv_bfloat16* __restrict__ tl) {
    __shared__ float tile[32][33];
    const int b = blockIdx.z, c0 = blockIdx.y << 5, l0 = blockIdx.x << 5;
    const int tx = threadIdx.x, ty = threadIdx.y;   // (32, 8)
    const float* xb = x + ((size_t)b * C_SZ + c0) * L_SZ + l0;
#pragma unroll
    for (int r = ty; r < 32; r += 8)
        tile[r][tx] = xb[(size_t)r * L_SZ + tx];
    __syncthreads();
    size_t ob = ((size_t)b * L_SZ + l0) * C_SZ + c0;
#pragma unroll
    for (int r = ty; r < 32; r += 8) {
        float v = tile[tx][r];
        __nv_bfloat16 h, l; split_bf16(v, h, l);
        th[ob + (size_t)r * C_SZ + tx] = h;
        tl[ob + (size_t)r * C_SZ + tx] = l;
    }
}

// ======================= fold BN scale into W, split =======================
__global__ __launch_bounds__(256) void w_scale_split(
    const float* __restrict__ W, const float* __restrict__ gamma,
    __nv_bfloat16* __restrict__ wh, __nv_bfloat16* __restrict__ wl) {
    int i = blockIdx.x * 256 + threadIdx.x;
    int c = i & (C_SZ - 1);
    float v = W[i] * (g_rstd[c] * gamma[c]);
    __nv_bfloat16 h, l; split_bf16(v, h, l);
    wh[i] = h; wl[i] = l;
}

// plain split (no BN fold) — for Wp
__global__ __launch_bounds__(256) void w_split_plain(
    const float* __restrict__ W,
    __nv_bfloat16* __restrict__ wh, __nv_bfloat16* __restrict__ wl) {
    int i = blockIdx.x * 256 + threadIdx.x;
    float v = W[i];
    __nv_bfloat16 h, l; split_bf16(v, h, l);
    wh[i] = h; wl[i] = l;
}

// b'[o] = b[o] + sum_c W[o,c] * (beta[c] - mean[c]*s[c])
__global__ __launch_bounds__(128) void bias_fold(
    const float* __restrict__ W, const float* __restrict__ b,
    const float* __restrict__ gamma, const float* __restrict__ beta,
    float* __restrict__ bout) {
    const int o = blockIdx.x;
    float acc = 0.f;
    for (int c = threadIdx.x; c < C_SZ; c += 128) {
        float s = g_rstd[c] * gamma[c];
        float t = beta[c] - g_mean[c] * s;
        acc += W[o * C_SZ + c] * t;
    }
    __shared__ float sh[128];
    sh[threadIdx.x] = acc;
    __syncthreads();
    for (int o2 = 64; o2 > 0; o2 >>= 1) {
        if (threadIdx.x < o2) sh[threadIdx.x] += sh[threadIdx.x + o2];
        __syncthreads();
    }
    if (threadIdx.x == 0) bout[o] = b[o] + sh[0];
}

// ======================= mma.sync split-bf16 GEMM (padded smem) =======================
// D[m,n] = sum_k A[m,k]*B[n,k], both K-major, hi/lo split (3 HMMA products).
// CTA tile 128x128, BK=64, double-buffered cp.async, 8 warps of 32x64.
// smem: 128 rows x 64 bf16, pitch 144B (conflict-free LDS.32 fragments).
// EPI 0: bf16-split out, bias per-n
// EPI 1: bf16-split out, bias per-m
// EPI 2: bf16-split out, no bias
// EPI 3: fp32 * alpha out
// EPI 4: fp32 + bias per-m + residual out
#define PITCH 144
#define TILE_B (128 * PITCH)              // 18432
#define STAGE_BYTES (4 * TILE_B)          // 73728
#define SMEM_GEMM_BYTES (2 * STAGE_BYTES) // 147456

template <int EPI>
__global__ void __launch_bounds__(256, 1) mma_gemm(
    const __nv_bfloat16* __restrict__ Ahi, const __nv_bfloat16* __restrict__ Alo,
    const __nv_bfloat16* __restrict__ Bhi, const __nv_bfloat16* __restrict__ Blo,
    const float* __restrict__ bias, const float* __restrict__ res,
    void* outA, void* outB,
    int K, int ldA, int ldB, int ldO,
    long sA, long sB, long sO, long sRes, float alpha) {
    extern __shared__ char smem[];
    const uint32_t sb = smem_to_u32(smem);
    const int tid = threadIdx.x, lane = tid & 31, wid = tid >> 5;
    const int bz = blockIdx.z;
    const int m0 = blockIdx.y << 7, n0 = blockIdx.x << 7;

    const char* gAh = (const char*)(Ahi + (size_t)bz * sA);
    const char* gAl = (const char*)(Alo + (size_t)bz * sA);
    const char* gBh = (const char*)(Bhi + (size_t)bz * sB);
    const char* gBl = (const char*)(Blo + (size_t)bz * sB);
    const size_t ldA2 = (size_t)ldA * 2, ldB2 = (size_t)ldB * 2;

    const int wm = (wid & 3) * 32;
    const int wn = (wid >> 2) * 64;

    float acc[2][8][4];
#pragma unroll
    for (int a = 0; a < 2; a++)
#pragma unroll
        for (int b = 0; b < 8; b++)
#pragma unroll
            for (int c = 0; c < 4; c++) acc[a][b][c] = 0.f;

    const int nst = K >> 6;

    auto prefetch = [&](int s) {
        uint32_t st = sb + (uint32_t)(s & 1) * STAGE_BYTES;
        size_t kb = (size_t)s * 128;
#pragma unroll
        for (int i = 0; i < 4; i++) {
            int idx = tid + (i << 8);
            int row = idx >> 3, ch = idx & 7;
            uint32_t doff = (uint32_t)row * PITCH + (uint32_t)ch * 16u;
            size_t aoff = (size_t)(m0 + row) * ldA2 + kb + (size_t)ch * 16;
            size_t boff = (size_t)(n0 + row) * ldB2 + kb + (size_t)ch * 16;
            cp16(st + doff,               gAh + aoff);
            cp16(st + TILE_B + doff,      gAl + aoff);
            cp16(st + 2 * TILE_B + doff,  gBh + boff);
            cp16(st + 3 * TILE_B + doff,  gBl + boff);
        }
        cp_commit();
    };

    prefetch(0);

    const int quad = lane >> 2;
    const int qr   = lane & 3;
    const uint32_t fr_off = (uint32_t)quad * PITCH + (uint32_t)qr * 4u;

    for (int s = 0; s < nst; s++) {
        if (s + 1 < nst) { prefetch(s + 1); cp_wait<1>(); }
        else             { cp_wait<0>(); }
        __syncthreads();
        const uint32_t st = sb + (uint32_t)(s & 1) * STAGE_BYTES;
#pragma unroll
        for (int kk = 0; kk < 4; kk++) {
            const uint32_t kb32 = (uint32_t)kk * 32u;
            uint32_t ah[2][4], al_[2][4], bh[4][4], bl_[4][4];
#pragma unroll
            for (int mi = 0; mi < 2; mi++) {
                uint32_t a0 = st + (uint32_t)(wm + mi * 16) * PITCH + kb32 + fr_off;
                ah[mi][0] = lds32(a0);
                ah[mi][1] = lds32(a0 + 8 * PITCH);
                ah[mi][2] = lds32(a0 + 16);
                ah[mi][3] = lds32(a0 + 8 * PITCH + 16);
                uint32_t a0l = a0 + TILE_B;
                al_[mi][0] = lds32(a0l);
                al_[mi][1] = lds32(a0l + 8 * PITCH);
                al_[mi][2] = lds32(a0l + 16);
                al_[mi][3] = lds32(a0l + 8 * PITCH + 16);
            }
#pragma unroll
            for (int ni = 0; ni < 4; ni++) {
                uint32_t b0 = st + 2 * TILE_B + (uint32_t)(wn + ni * 16) * PITCH + kb32 + fr_off;
                bh[ni][0] = lds32(b0);
                bh[ni][1] = lds32(b0 + 16);
                bh[ni][2] = lds32(b0 + 8 * PITCH);
                bh[ni][3] = lds32(b0 + 8 * PITCH + 16);
                uint32_t b0l = b0 + TILE_B;
                bl_[ni][0] = lds32(b0l);
                bl_[ni][1] = lds32(b0l + 16);
                bl_[ni][2] = lds32(b0l + 8 * PITCH);
                bl_[ni][3] = lds32(b0l + 8 * PITCH + 16);
            }
#pragma unroll
            for (int mi = 0; mi < 2; mi++)
#pragma unroll
                for (int n8 = 0; n8 < 8; n8++) {
                    int ni = n8 >> 1, hf = (n8 & 1) * 2;
                    mma16816(acc[mi][n8], ah[mi],  bh[ni][hf],  bh[ni][hf + 1]);
                    mma16816(acc[mi][n8], ah[mi],  bl_[ni][hf], bl_[ni][hf + 1]);
                    mma16816(acc[mi][n8], al_[mi], bh[ni][hf],  bh[ni][hf + 1]);
                }
        }
        __syncthreads();
    }

    // ---------------- epilogue ----------------
#pragma unroll
    for (int mi = 0; mi < 2; mi++) {
        const int r0 = m0 + wm + mi * 16 + (lane >> 2);
        const int r1 = r0 + 8;
#pragma unroll
        for (int n8 = 0; n8 < 8; n8++) {
            const int col = n0 + wn + n8 * 8 + 2 * (lane & 3);
            float* a4 = acc[mi][n8];
            if (EPI == 3) {
                float* o = (float*)outA + (size_t)bz * sO;
                float2 v0 = make_float2(a4[0] * alpha, a4[1] * alpha);
                float2 v1 = make_float2(a4[2] * alpha, a4[3] * alpha);
                *(float2*)(o + (size_t)r0 * ldO + col) = v0;
                *(float2*)(o + (size_t)r1 * ldO + col) = v1;
            } else if (EPI == 4) {
                float* o = (float*)outA + (size_t)bz * sO;
                const float* rp = res + (size_t)bz * sRes;
                float bi0 = bias[r0], bi1 = bias[r1];
                float2 q0 = *(const float2*)(rp + (size_t)r0 * ldO + col);
                float2 q1 = *(const float2*)(rp + (size_t)r1 * ldO + col);
                float2 v0 = make_float2(a4[0] + bi0 + q0.x, a4[1] + bi0 + q0.y);
                float2 v1 = make_float2(a4[2] + bi1 + q1.x, a4[3] + bi1 + q1.y);
                *(float2*)(o + (size_t)r0 * ldO + col) = v0;
                *(float2*)(o + (size_t)r1 * ldO + col) = v1;
            } else {
                float b00 = 0.f, b01 = 0.f, b10 = 0.f, b11 = 0.f;
                if (EPI == 0) { float bn0 = bias[col], bn1 = bias[col + 1]; b00 = bn0; b01 = bn1; b10 = bn0; b11 = bn1; }
                if (EPI == 1) { float bm0 = bias[r0], bm1 = bias[r1]; b00 = bm0; b01 = bm0; b10 = bm1; b11 = bm1; }
                __nv_bfloat16 h0, l0, h1, l1, h2, l2, h3, l3;
                split_bf16(a4[0] + b00, h0, l0);
                split_bf16(a4[1] + b01, h1, l1);
                split_bf16(a4[2] + b10, h2, l2);
                split_bf16(a4[3] + b11, h3, l3);
                __nv_bfloat16* oh = (__nv_bfloat16*)outA + (size_t)bz * sO;
                __nv_bfloat16* ol = (__nv_bfloat16*)outB + (size_t)bz * sO;
                *(uint32_t*)(oh + (size_t)r0 * ldO + col) = pack_bf16(h0, h1);
                *(uint32_t*)(oh + (size_t)r1 * ldO + col) = pack_bf16(h2, h3);
                *(uint32_t*)(ol + (size_t)r0 * ldO + col) = pack_bf16(l0, l1);
                *(uint32_t*)(ol + (size_t)r1 * ldO + col) = pack_bf16(l2, l3);
            }
        }
    }
}

// ======================= softmax + bf16 split =======================
__global__ __launch_bounds__(256) void softmax_split(
    const float* __restrict__ sc,
    __nv_bfloat16* __restrict__ ah, __nv_bfloat16* __restrict__ al) {
    const size_t row = blockIdx.x;
    const float4* p4 = (const float4*)(sc + row * L_SZ);
    const int t = threadIdx.x;
    float4 v = p4[t];
    __shared__ float sh[256];
    float mx = fmaxf(fmaxf(v.x, v.y), fmaxf(v.z, v.w));
    sh[t] = mx; __syncthreads();
    for (int o = 128; o > 0; o >>= 1) {
        if (t < o) sh[t] = fmaxf(sh[t], sh[t + o]);
        __syncthreads();
    }
    mx = sh[0]; __syncthreads();
    v.x = expf(v.x - mx); v.y = expf(v.y - mx);
    v.z = expf(v.z - mx); v.w = expf(v.w - mx);
    sh[t] = v.x + v.y + v.z + v.w; __syncthreads();
    for (int o = 128; o > 0; o >>= 1) {
        if (t < o) sh[t] += sh[t + o];
        __syncthreads();
    }
    float inv = 1.f / sh[0];
    __nv_bfloat16 h0, l0, h1, l1, h2, l2, h3, l3;
    split_bf16(v.x * inv, h0, l0); split_bf16(v.y * inv, h1, l1);
    split_bf16(v.z * inv, h2, l2); split_bf16(v.w * inv, h3, l3);
    ((uint2*)(ah + row * L_SZ))[t] = make_uint2(pack_bf16(h0, h1), pack_bf16(h2, h3));
    ((uint2*)(al + row * L_SZ))[t] = make_uint2(pack_bf16(l0, l1), pack_bf16(l2, l3));
}

// ======================= launch =======================
extern "C" void kernel_launch(void* const* d_in, const int* in_sizes, int n_in,
                              void* d_out, int out_size) {
    const float* x     = (const float*)d_in[0];
    const float* gamma = (const float*)d_in[1];
    const float* beta  = (const float*)d_in[2];
    const float* Wq = (const float*)d_in[3];  const float* bq = (const float*)d_in[4];
    const float* Wk = (const float*)d_in[5];  const float* bk = (const float*)d_in[6];
    const float* Wv = (const float*)d_in[7];  const float* bv = (const float*)d_in[8];
    const float* Wp = (const float*)d_in[9];  const float* bp = (const float*)d_in[10];
    float* out = (float*)d_out;

    __nv_bfloat16 *xt_hi, *xt_lo, *w_hi, *w_lo, *qt_hi, *qt_lo, *kt_hi, *kt_lo;
    __nv_bfloat16 *v_hi, *v_lo, *at_hi, *at_lo, *ht_hi, *ht_lo;
    float *scores, *bfold;
    cudaGetSymbolAddress((void**)&xt_hi, g_xt_hi);
    cudaGetSymbolAddress((void**)&xt_lo, g_xt_lo);
    cudaGetSymbolAddress((void**)&w_hi, g_w_hi);
    cudaGetSymbolAddress((void**)&w_lo, g_w_lo);
    cudaGetSymbolAddress((void**)&bfold, g_bfold);
    cudaGetSymbolAddress((void**)&qt_hi, g_qt_hi);
    cudaGetSymbolAddress((void**)&qt_lo, g_qt_lo);
    cudaGetSymbolAddress((void**)&kt_hi, g_kt_hi);
    cudaGetSymbolAddress((void**)&kt_lo, g_kt_lo);
    cudaGetSymbolAddress((void**)&v_hi, g_v_hi);
    cudaGetSymbolAddress((void**)&v_lo, g_v_lo);
    cudaGetSymbolAddress((void**)&scores, g_scores);
    cudaGetSymbolAddress((void**)&at_hi, g_at_hi);
    cudaGetSymbolAddress((void**)&at_lo, g_at_lo);
    cudaGetSymbolAddress((void**)&ht_hi, g_ht_hi);
    cudaGetSymbolAddress((void**)&ht_lo, g_ht_lo);

    cudaFuncSetAttribute(mma_gemm<0>, cudaFuncAttributeMaxDynamicSharedMemorySize, SMEM_GEMM_BYTES);
    cudaFuncSetAttribute(mma_gemm<1>, cudaFuncAttributeMaxDynamicSharedMemorySize, SMEM_GEMM_BYTES);
    cudaFuncSetAttribute(mma_gemm<2>, cudaFuncAttributeMaxDynamicSharedMemorySize, SMEM_GEMM_BYTES);
    cudaFuncSetAttribute(mma_gemm<3>, cudaFuncAttributeMaxDynamicSharedMemorySize, SMEM_GEMM_BYTES);
    cudaFuncSetAttribute(mma_gemm<4>, cudaFuncAttributeMaxDynamicSharedMemorySize, SMEM_GEMM_BYTES);

    const int CC = C_SZ * C_SZ;

    // 1. BN stats (feeds the weight/bias folds only)
    bn_stats<<<C_SZ, 256>>>(x);
    // 2. raw x -> transposed bf16 split [B,L,C]  (BN folded into W, NOT applied here)
    transpose_split<<<dim3(32, 16, 16), dim3(32, 8)>>>(x, xt_hi, xt_lo);
    // 3. fold BN into Wq/Wk/Wv + biases; Wp/bp stay plain
    w_scale_split<<<CC / 256, 256>>>(Wq, gamma, w_hi + 0 * CC, w_lo + 0 * CC);
    w_scale_split<<<CC / 256, 256>>>(Wk, gamma, w_hi + 1 * CC, w_lo + 1 * CC);
    w_scale_split<<<CC / 256, 256>>>(Wv, gamma, w_hi + 2 * CC, w_lo + 2 * CC);
    w_split_plain<<<CC / 256, 256>>>(Wp, w_hi + 3 * CC, w_lo + 3 * CC);
    bias_fold<<<C_SZ, 128>>>(Wq, bq, gamma, beta, bfold + 0 * C_SZ);
    bias_fold<<<C_SZ, 128>>>(Wk, bk, gamma, beta, bfold + 1 * C_SZ);
    bias_fold<<<C_SZ, 128>>>(Wv, bv, gamma, beta, bfold + 2 * C_SZ);

    // 4. qt[l,c] = xt[l,:]·Wq'[c,:] + bq'  (M=L, N=C, bias per-n)
    mma_gemm<0><<<dim3(4, 8, 16), 256, SMEM_GEMM_BYTES>>>(
        xt_hi, xt_lo, w_hi + 0 * CC, w_lo + 0 * CC, bfold + 0 * C_SZ, nullptr,
        qt_hi, qt_lo, C_SZ, C_SZ, C_SZ, C_SZ, CL, 0, CL, 0, 0.f);
    mma_gemm<0><<<dim3(4, 8, 16), 256, SMEM_GEMM_BYTES>>>(
        xt_hi, xt_lo, w_hi + 1 * CC, w_lo + 1 * CC, bfold + 1 * C_SZ, nullptr,
        kt_hi, kt_lo, C_SZ, C_SZ, C_SZ, C_SZ, CL, 0, CL, 0, 0.f);
    // 5. v[c,l] = Wv'[c,:]·xt[l,:] + bv'  (M=C, N=L, bias per-m)
    mma_gemm<1><<<dim3(8, 4, 16), 256, SMEM_GEMM_BYTES>>>(
        w_hi + 2 * CC, w_lo + 2 * CC, xt_hi, xt_lo, bfold + 2 * C_SZ, nullptr,
        v_hi, v_lo, C_SZ, C_SZ, C_SZ, L_SZ, 0, CL, CL, 0, 0.f);

    // 6. scores[i,j] = alpha * qt[i,:]·kt[j,:]
    const float alpha = 1.f / sqrtf((float)C_SZ);
    mma_gemm<3><<<dim3(8, 8, 16), 256, SMEM_GEMM_BYTES>>>(
        qt_hi, qt_lo, kt_hi, kt_lo, nullptr, nullptr,
        scores, nullptr, C_SZ, C_SZ, C_SZ, L_SZ, CL, CL, LL, 0, alpha);

    // 7. softmax -> bf16 split probs [B,L,L]
    softmax_split<<<B_SZ * L_SZ, 256>>>(scores, at_hi, at_lo);

    // 8. ht[i,c] = at[i,:]·v[c,:]  (M=L, N=C, K=L, no bias)
    mma_gemm<2><<<dim3(4, 8, 16), 256, SMEM_GEMM_BYTES>>>(
        at_hi, at_lo, v_hi, v_lo, nullptr, nullptr,
        ht_hi, ht_lo, L_SZ, L_SZ, L_SZ, C_SZ, LL, CL, CL, 0, 0.f);

    // 9. out[c,l] = Wp[c,:]·ht[l,:] + bp + x[c,l]  (plain Wp/bp, residual)
    mma_gemm<4><<<dim3(8, 4, 16), 256, SMEM_GEMM_BYTES>>>(
        w_hi + 3 * CC, w_lo + 3 * CC, ht_hi, ht_lo, bp, x,
        out, nullptr, C_SZ, C_SZ, C_SZ, L_SZ, 0, CL, CL, CL, 0.f);
}

// round 8
// speedup vs baseline: 2.8014x; 1.1493x over previous
#include <cuda_runtime.h>
#include <cuda_bf16.h>
#include <cstdint>
#include <math.h>

#define B_SZ 16
#define C_SZ 512
#define L_SZ 1024
#define BN_EPS 1e-5f
#define CL (C_SZ * L_SZ)        // 524288
#define LL (L_SZ * L_SZ)        // 1048576

// ======================= scratch (static device globals) =======================
__device__ float g_mean[C_SZ];
__device__ float g_rstd[C_SZ];
__device__ __nv_bfloat16 g_xt_hi[B_SZ * CL];   // RAW x, transposed [B,L,C], split
__device__ __nv_bfloat16 g_xt_lo[B_SZ * CL];
__device__ __nv_bfloat16 g_w_hi[4 * C_SZ * C_SZ];  // Wq',Wk',Wv' (BN-folded), Wp (plain)
__device__ __nv_bfloat16 g_w_lo[4 * C_SZ * C_SZ];
__device__ float g_bfold[3 * C_SZ];            // folded biases for q,k,v
__device__ __nv_bfloat16 g_qt_hi[B_SZ * CL];   // q transposed [B,L,C]
__device__ __nv_bfloat16 g_qt_lo[B_SZ * CL];
__device__ __nv_bfloat16 g_kt_hi[B_SZ * CL];
__device__ __nv_bfloat16 g_kt_lo[B_SZ * CL];
__device__ __nv_bfloat16 g_v_hi[B_SZ * CL];    // v natural [B,C,L]
__device__ __nv_bfloat16 g_v_lo[B_SZ * CL];
__device__ float g_scores[B_SZ * LL];
__device__ __nv_bfloat16 g_at_hi[B_SZ * LL];   // attn probs [B,L,L]
__device__ __nv_bfloat16 g_at_lo[B_SZ * LL];
__device__ __nv_bfloat16 g_ht_hi[B_SZ * CL];   // h_ transposed [B,L,C]
__device__ __nv_bfloat16 g_ht_lo[B_SZ * CL];

// ======================= helpers =======================
__device__ __forceinline__ uint32_t smem_to_u32(const void* p) {
    uint32_t a;
    asm("{ .reg .u64 t; cvta.to.shared.u64 t, %1; cvt.u32.u64 %0, t; }" : "=r"(a) : "l"(p));
    return a;
}
#define SWZ128(off) ((off) ^ (((off) >> 3) & 0x70))

__device__ __forceinline__ void cp16(uint32_t dst, const void* src) {
    asm volatile("cp.async.cg.shared.global [%0], [%1], 16;" :: "r"(dst), "l"(src));
}
__device__ __forceinline__ void cp_commit() {
    asm volatile("cp.async.commit_group;");
}
template <int N>
__device__ __forceinline__ void cp_wait() {
    asm volatile("cp.async.wait_group %0;" :: "n"(N));
}
__device__ __forceinline__ void ldsm4(uint32_t* r, uint32_t addr) {
    asm volatile("ldmatrix.sync.aligned.m8n8.x4.shared.b16 {%0,%1,%2,%3}, [%4];"
                 : "=r"(r[0]), "=r"(r[1]), "=r"(r[2]), "=r"(r[3]) : "r"(addr));
}
__device__ __forceinline__ void mma16816(float* c, const uint32_t* a, uint32_t b0, uint32_t b1) {
    asm volatile(
        "mma.sync.aligned.m16n8k16.row.col.f32.bf16.bf16.f32 "
        "{%0,%1,%2,%3}, {%4,%5,%6,%7}, {%8,%9}, {%0,%1,%2,%3};"
        : "+f"(c[0]), "+f"(c[1]), "+f"(c[2]), "+f"(c[3])
        : "r"(a[0]), "r"(a[1]), "r"(a[2]), "r"(a[3]), "r"(b0), "r"(b1));
}
__device__ __forceinline__ void split_bf16(float v, __nv_bfloat16& h, __nv_bfloat16& l) {
    h = __float2bfloat16(v);
    l = __float2bfloat16(v - __bfloat162float(h));
}
__device__ __forceinline__ uint32_t pack_bf16(__nv_bfloat16 a, __nv_bfloat16 b) {
    return (uint32_t)__bfloat16_as_ushort(a) | ((uint32_t)__bfloat16_as_ushort(b) << 16);
}

// ======================= BatchNorm stats =======================
__global__ __launch_bounds__(256) void bn_stats(const float* __restrict__ x) {
    const int c = blockIdx.x;
    const float* xc = x + (size_t)c * L_SZ;
    float s = 0.f, ss = 0.f;
    for (int idx = threadIdx.x; idx < B_SZ * L_SZ; idx += 256) {
        int b = idx >> 10, l = idx & (L_SZ - 1);
        float v = xc[(size_t)b * CL + l];
        s += v; ss += v * v;
    }
    __shared__ float shs[256], shq[256];
    shs[threadIdx.x] = s; shq[threadIdx.x] = ss;
    __syncthreads();
    for (int o = 128; o > 0; o >>= 1) {
        if (threadIdx.x < o) { shs[threadIdx.x] += shs[threadIdx.x + o]; shq[threadIdx.x] += shq[threadIdx.x + o]; }
        __syncthreads();
    }
    if (threadIdx.x == 0) {
        const float inv_n = 1.f / (float)(B_SZ * L_SZ);
        float m = shs[0] * inv_n;
        float var = shq[0] * inv_n - m * m;
        g_mean[c] = m;
        g_rstd[c] = rsqrtf(var + BN_EPS);
    }
}

// ======================= x -> RAW transposed, bf16-split =======================
__global__ __launch_bounds__(256) void transpose_split(
    const float* __restrict__ x,
    __nv_bfloat16* __restrict__ th, __nv_bfloat16* __restrict__ tl) {
    __shared__ float tile[32][33];
    const int b = blockIdx.z, c0 = blockIdx.y << 5, l0 = blockIdx.x << 5;
    const int tx = threadIdx.x, ty = threadIdx.y;   // (32, 8)
    const float* xb = x + ((size_t)b * C_SZ + c0) * L_SZ + l0;
#pragma unroll
    for (int r = ty; r < 32; r += 8)
        tile[r][tx] = xb[(size_t)r * L_SZ + tx];
    __syncthreads();
    size_t ob = ((size_t)b * L_SZ + l0) * C_SZ + c0;
#pragma unroll
    for (int r = ty; r < 32; r += 8) {
        float v = tile[tx][r];
        __nv_bfloat16 h, l; split_bf16(v, h, l);
        th[ob + (size_t)r * C_SZ + tx] = h;
        tl[ob + (size_t)r * C_SZ + tx] = l;
    }
}

// ======================= fold BN scale into W, split =======================
__global__ __launch_bounds__(256) void w_scale_split(
    const float* __restrict__ W, const float* __restrict__ gamma,
    __nv_bfloat16* __restrict__ wh, __nv_bfloat16* __restrict__ wl) {
    int i = blockIdx.x * 256 + threadIdx.x;
    int c = i & (C_SZ - 1);
    float v = W[i] * (g_rstd[c] * gamma[c]);
    __nv_bfloat16 h, l; split_bf16(v, h, l);
    wh[i] = h; wl[i] = l;
}

__global__ __launch_bounds__(256) void w_split_plain(
    const float* __restrict__ W,
    __nv_bfloat16* __restrict__ wh, __nv_bfloat16* __restrict__ wl) {
    int i = blockIdx.x * 256 + threadIdx.x;
    float v = W[i];
    __nv_bfloat16 h, l; split_bf16(v, h, l);
    wh[i] = h; wl[i] = l;
}

// b'[o] = b[o] + sum_c W[o,c] * (beta[c] - mean[c]*s[c])
__global__ __launch_bounds__(128) void bias_fold(
    const float* __restrict__ W, const float* __restrict__ b,
    const float* __restrict__ gamma, const float* __restrict__ beta,
    float* __restrict__ bout) {
    const int o = blockIdx.x;
    float acc = 0.f;
    for (int c = threadIdx.x; c < C_SZ; c += 128) {
        float s = g_rstd[c] * gamma[c];
        float t = beta[c] - g_mean[c] * s;
        acc += W[o * C_SZ + c] * t;
    }
    __shared__ float sh[128];
    sh[threadIdx.x] = acc;
    __syncthreads();
    for (int o2 = 64; o2 > 0; o2 >>= 1) {
        if (threadIdx.x < o2) sh[threadIdx.x] += sh[threadIdx.x + o2];
        __syncthreads();
    }
    if (threadIdx.x == 0) bout[o] = b[o] + sh[0];
}

// ======================= mma.sync split-bf16 GEMM (SW128 + ldmatrix.x4) =======================
// D[m,n] = sum_k A[m,k]*B[n,k], both K-major, hi/lo split (3 HMMA products).
// CTA tile 128x128, BK=64, double-buffered cp.async, 8 warps of 32x64.
// smem: 4 tiles of 128 rows x 128B, SW128 swizzled; fragments via ldmatrix.x4.
// EPI 0: bf16-split out, bias per-n
// EPI 1: bf16-split out, bias per-m
// EPI 2: bf16-split out, no bias
// EPI 3: fp32 * alpha out
// EPI 4: fp32 + bias per-m + residual out
#define STAGE_BYTES 65536
#define SMEM_GEMM_BYTES (2 * STAGE_BYTES)

template <int EPI>
__global__ void __launch_bounds__(256, 1) mma_gemm(
    const __nv_bfloat16* __restrict__ Ahi, const __nv_bfloat16* __restrict__ Alo,
    const __nv_bfloat16* __restrict__ Bhi, const __nv_bfloat16* __restrict__ Blo,
    const float* __restrict__ bias, const float* __restrict__ res,
    void* outA, void* outB,
    int K, int ldA, int ldB, int ldO,
    long sA, long sB, long sO, long sRes, float alpha) {
    extern __shared__ char smem[];
    const uint32_t sb = smem_to_u32(smem);
    const int tid = threadIdx.x, lane = tid & 31, wid = tid >> 5;
    const int bz = blockIdx.z;
    const int m0 = blockIdx.y << 7, n0 = blockIdx.x << 7;

    const char* gAh = (const char*)(Ahi + (size_t)bz * sA);
    const char* gAl = (const char*)(Alo + (size_t)bz * sA);
    const char* gBh = (const char*)(Bhi + (size_t)bz * sB);
    const char* gBl = (const char*)(Blo + (size_t)bz * sB);
    const size_t ldA2 = (size_t)ldA * 2, ldB2 = (size_t)ldB * 2;

    const int wm = (wid & 3) * 32;     // warp m offset
    const int wn = (wid >> 2) * 64;    // warp n offset

    float acc[2][8][4];
#pragma unroll
    for (int a = 0; a < 2; a++)
#pragma unroll
        for (int b = 0; b < 8; b++)
#pragma unroll
            for (int c = 0; c < 4; c++) acc[a][b][c] = 0.f;

    const int nst = K >> 6;

    auto prefetch = [&](int s) {
        uint32_t st = sb + (uint32_t)(s & 1) * STAGE_BYTES;
        size_t kb = (size_t)s * 128;   // 64 bf16 = 128B along K
#pragma unroll
        for (int i = 0; i < 4; i++) {
            int idx = tid + (i << 8);
            int row = idx >> 3, ch = idx & 7;
            uint32_t doff = SWZ128((uint32_t)row * 128u + (uint32_t)ch * 16u);
            size_t aoff = (size_t)(m0 + row) * ldA2 + kb + (size_t)ch * 16;
            size_t boff = (size_t)(n0 + row) * ldB2 + kb + (size_t)ch * 16;
            cp16(st + doff,           gAh + aoff);
            cp16(st + 16384u + doff,  gAl + aoff);
            cp16(st + 32768u + doff,  gBh + boff);
            cp16(st + 49152u + doff,  gBl + boff);
        }
        cp_commit();
    };

    prefetch(0);

    // ldmatrix lane address components (canonical x4 patterns)
    const int a_row  = (lane & 7) + ((lane >> 3) & 1) * 8;
    const int a_koff = (lane >> 4) * 16;                     // bytes
    const int b_row  = (lane & 7) + (lane >> 4) * 8;
    const int b_koff = ((lane >> 3) & 1) * 16;

    for (int s = 0; s < nst; s++) {
        if (s + 1 < nst) { prefetch(s + 1); cp_wait<1>(); }
        else             { cp_wait<0>(); }
        __syncthreads();
        const uint32_t st = sb + (uint32_t)(s & 1) * STAGE_BYTES;
#pragma unroll
        for (int kk = 0; kk < 4; kk++) {
            uint32_t ah[2][4], al_[2][4], bh[4][4], bl_[4][4];
#pragma unroll
            for (int mi = 0; mi < 2; mi++) {
                uint32_t off = SWZ128((uint32_t)((wm + mi * 16 + a_row) * 128 + kk * 32 + a_koff));
                ldsm4(ah[mi], st + off);
                ldsm4(al_[mi], st + 16384u + off);
            }
#pragma unroll
            for (int ni = 0; ni < 4; ni++) {
                uint32_t off = SWZ128((uint32_t)((wn + ni * 16 + b_row) * 128 + kk * 32 + b_koff));
                ldsm4(bh[ni], st + 32768u + off);
                ldsm4(bl_[ni], st + 49152u + off);
            }
#pragma unroll
            for (int mi = 0; mi < 2; mi++)
#pragma unroll
                for (int n8 = 0; n8 < 8; n8++) {
                    int ni = n8 >> 1, hf = (n8 & 1) * 2;
                    mma16816(acc[mi][n8], ah[mi],  bh[ni][hf],  bh[ni][hf + 1]);
                    mma16816(acc[mi][n8], ah[mi],  bl_[ni][hf], bl_[ni][hf + 1]);
                    mma16816(acc[mi][n8], al_[mi], bh[ni][hf],  bh[ni][hf + 1]);
                }
        }
        __syncthreads();
    }

    // ---------------- epilogue ----------------
#pragma unroll
    for (int mi = 0; mi < 2; mi++) {
        const int r0 = m0 + wm + mi * 16 + (lane >> 2);
        const int r1 = r0 + 8;
#pragma unroll
        for (int n8 = 0; n8 < 8; n8++) {
            const int col = n0 + wn + n8 * 8 + 2 * (lane & 3);
            float* a4 = acc[mi][n8];
            if (EPI == 3) {
                float* o = (float*)outA + (size_t)bz * sO;
                float2 v0 = make_float2(a4[0] * alpha, a4[1] * alpha);
                float2 v1 = make_float2(a4[2] * alpha, a4[3] * alpha);
                *(float2*)(o + (size_t)r0 * ldO + col) = v0;
                *(float2*)(o + (size_t)r1 * ldO + col) = v1;
            } else if (EPI == 4) {
                float* o = (float*)outA + (size_t)bz * sO;
                const float* rp = res + (size_t)bz * sRes;
                float bi0 = bias[r0], bi1 = bias[r1];
                float2 q0 = *(const float2*)(rp + (size_t)r0 * ldO + col);
                float2 q1 = *(const float2*)(rp + (size_t)r1 * ldO + col);
                float2 v0 = make_float2(a4[0] + bi0 + q0.x, a4[1] + bi0 + q0.y);
                float2 v1 = make_float2(a4[2] + bi1 + q1.x, a4[3] + bi1 + q1.y);
                *(float2*)(o + (size_t)r0 * ldO + col) = v0;
                *(float2*)(o + (size_t)r1 * ldO + col) = v1;
            } else {
                float b00 = 0.f, b01 = 0.f, b10 = 0.f, b11 = 0.f;
                if (EPI == 0) { float bn0 = bias[col], bn1 = bias[col + 1]; b00 = bn0; b01 = bn1; b10 = bn0; b11 = bn1; }
                if (EPI == 1) { float bm0 = bias[r0], bm1 = bias[r1]; b00 = bm0; b01 = bm0; b10 = bm1; b11 = bm1; }
                __nv_bfloat16 h0, l0, h1, l1, h2, l2, h3, l3;
                split_bf16(a4[0] + b00, h0, l0);
                split_bf16(a4[1] + b01, h1, l1);
                split_bf16(a4[2] + b10, h2, l2);
                split_bf16(a4[3] + b11, h3, l3);
                __nv_bfloat16* oh = (__nv_bfloat16*)outA + (size_t)bz * sO;
                __nv_bfloat16* ol = (__nv_bfloat16*)outB + (size_t)bz * sO;
                *(uint32_t*)(oh + (size_t)r0 * ldO + col) = pack_bf16(h0, h1);
                *(uint32_t*)(oh + (size_t)r1 * ldO + col) = pack_bf16(h2, h3);
                *(uint32_t*)(ol + (size_t)r0 * ldO + col) = pack_bf16(l0, l1);
                *(uint32_t*)(ol + (size_t)r1 * ldO + col) = pack_bf16(l2, l3);
            }
        }
    }
}

// ======================= softmax + bf16 split =======================
__global__ __launch_bounds__(256) void softmax_split(
    const float* __restrict__ sc,
    __nv_bfloat16* __restrict__ ah, __nv_bfloat16* __restrict__ al) {
    const size_t row = blockIdx.x;
    const float4* p4 = (const float4*)(sc + row * L_SZ);
    const int t = threadIdx.x;
    float4 v = p4[t];
    __shared__ float sh[256];
    float mx = fmaxf(fmaxf(v.x, v.y), fmaxf(v.z, v.w));
    sh[t] = mx; __syncthreads();
    for (int o = 128; o > 0; o >>= 1) {
        if (t < o) sh[t] = fmaxf(sh[t], sh[t + o]);
        __syncthreads();
    }
    mx = sh[0]; __syncthreads();
    v.x = expf(v.x - mx); v.y = expf(v.y - mx);
    v.z = expf(v.z - mx); v.w = expf(v.w - mx);
    sh[t] = v.x + v.y + v.z + v.w; __syncthreads();
    for (int o = 128; o > 0; o >>= 1) {
        if (t < o) sh[t] += sh[t + o];
        __syncthreads();
    }
    float inv = 1.f / sh[0];
    __nv_bfloat16 h0, l0, h1, l1, h2, l2, h3, l3;
    split_bf16(v.x * inv, h0, l0); split_bf16(v.y * inv, h1, l1);
    split_bf16(v.z * inv, h2, l2); split_bf16(v.w * inv, h3, l3);
    ((uint2*)(ah + row * L_SZ))[t] = make_uint2(pack_bf16(h0, h1), pack_bf16(h2, h3));
    ((uint2*)(al + row * L_SZ))[t] = make_uint2(pack_bf16(l0, l1), pack_bf16(l2, l3));
}

// ======================= launch =======================
extern "C" void kernel_launch(void* const* d_in, const int* in_sizes, int n_in,
                              void* d_out, int out_size) {
    const float* x     = (const float*)d_in[0];
    const float* gamma = (const float*)d_in[1];
    const float* beta  = (const float*)d_in[2];
    const float* Wq = (const float*)d_in[3];  const float* bq = (const float*)d_in[4];
    const float* Wk = (const float*)d_in[5];  const float* bk = (const float*)d_in[6];
    const float* Wv = (const float*)d_in[7];  const float* bv = (const float*)d_in[8];
    const float* Wp = (const float*)d_in[9];  const float* bp = (const float*)d_in[10];
    float* out = (float*)d_out;

    __nv_bfloat16 *xt_hi, *xt_lo, *w_hi, *w_lo, *qt_hi, *qt_lo, *kt_hi, *kt_lo;
    __nv_bfloat16 *v_hi, *v_lo, *at_hi, *at_lo, *ht_hi, *ht_lo;
    float *scores, *bfold;
    cudaGetSymbolAddress((void**)&xt_hi, g_xt_hi);
    cudaGetSymbolAddress((void**)&xt_lo, g_xt_lo);
    cudaGetSymbolAddress((void**)&w_hi, g_w_hi);
    cudaGetSymbolAddress((void**)&w_lo, g_w_lo);
    cudaGetSymbolAddress((void**)&bfold, g_bfold);
    cudaGetSymbolAddress((void**)&qt_hi, g_qt_hi);
    cudaGetSymbolAddress((void**)&qt_lo, g_qt_lo);
    cudaGetSymbolAddress((void**)&kt_hi, g_kt_hi);
    cudaGetSymbolAddress((void**)&kt_lo, g_kt_lo);
    cudaGetSymbolAddress((void**)&v_hi, g_v_hi);
    cudaGetSymbolAddress((void**)&v_lo, g_v_lo);
    cudaGetSymbolAddress((void**)&scores, g_scores);
    cudaGetSymbolAddress((void**)&at_hi, g_at_hi);
    cudaGetSymbolAddress((void**)&at_lo, g_at_lo);
    cudaGetSymbolAddress((void**)&ht_hi, g_ht_hi);
    cudaGetSymbolAddress((void**)&ht_lo, g_ht_lo);

    cudaFuncSetAttribute(mma_gemm<0>, cudaFuncAttributeMaxDynamicSharedMemorySize, SMEM_GEMM_BYTES);
    cudaFuncSetAttribute(mma_gemm<1>, cudaFuncAttributeMaxDynamicSharedMemorySize, SMEM_GEMM_BYTES);
    cudaFuncSetAttribute(mma_gemm<2>, cudaFuncAttributeMaxDynamicSharedMemorySize, SMEM_GEMM_BYTES);
    cudaFuncSetAttribute(mma_gemm<3>, cudaFuncAttributeMaxDynamicSharedMemorySize, SMEM_GEMM_BYTES);
    cudaFuncSetAttribute(mma_gemm<4>, cudaFuncAttributeMaxDynamicSharedMemorySize, SMEM_GEMM_BYTES);

    const int CC = C_SZ * C_SZ;

    // 1. BN stats (feeds the weight/bias folds only)
    bn_stats<<<C_SZ, 256>>>(x);
    // 2. raw x -> transposed bf16 split [B,L,C]
    transpose_split<<<dim3(32, 16, 16), dim3(32, 8)>>>(x, xt_hi, xt_lo);
    // 3. fold BN into Wq/Wk/Wv + biases; Wp/bp stay plain
    w_scale_split<<<CC / 256, 256>>>(Wq, gamma, w_hi + 0 * CC, w_lo + 0 * CC);
    w_scale_split<<<CC / 256, 256>>>(Wk, gamma, w_hi + 1 * CC, w_lo + 1 * CC);
    w_scale_split<<<CC / 256, 256>>>(Wv, gamma, w_hi + 2 * CC, w_lo + 2 * CC);
    w_split_plain<<<CC / 256, 256>>>(Wp, w_hi + 3 * CC, w_lo + 3 * CC);
    bias_fold<<<C_SZ, 128>>>(Wq, bq, gamma, beta, bfold + 0 * C_SZ);
    bias_fold<<<C_SZ, 128>>>(Wk, bk, gamma, beta, bfold + 1 * C_SZ);
    bias_fold<<<C_SZ, 128>>>(Wv, bv, gamma, beta, bfold + 2 * C_SZ);

    // 4. qt[l,c] = xt[l,:]·Wq'[c,:] + bq'  (M=L, N=C, bias per-n)
    mma_gemm<0><<<dim3(4, 8, 16), 256, SMEM_GEMM_BYTES>>>(
        xt_hi, xt_lo, w_hi + 0 * CC, w_lo + 0 * CC, bfold + 0 * C_SZ, nullptr,
        qt_hi, qt_lo, C_SZ, C_SZ, C_SZ, C_SZ, CL, 0, CL, 0, 0.f);
    mma_gemm<0><<<dim3(4, 8, 16), 256, SMEM_GEMM_BYTES>>>(
        xt_hi, xt_lo, w_hi + 1 * CC, w_lo + 1 * CC, bfold + 1 * C_SZ, nullptr,
        kt_hi, kt_lo, C_SZ, C_SZ, C_SZ, C_SZ, CL, 0, CL, 0, 0.f);
    // 5. v[c,l] = Wv'[c,:]·xt[l,:] + bv'  (M=C, N=L, bias per-m)
    mma_gemm<1><<<dim3(8, 4, 16), 256, SMEM_GEMM_BYTES>>>(
        w_hi + 2 * CC, w_lo + 2 * CC, xt_hi, xt_lo, bfold + 2 * C_SZ, nullptr,
        v_hi, v_lo, C_SZ, C_SZ, C_SZ, L_SZ, 0, CL, CL, 0, 0.f);

    // 6. scores[i,j] = alpha * qt[i,:]·kt[j,:]
    const float alpha = 1.f / sqrtf((float)C_SZ);
    mma_gemm<3><<<dim3(8, 8, 16), 256, SMEM_GEMM_BYTES>>>(
        qt_hi, qt_lo, kt_hi, kt_lo, nullptr, nullptr,
        scores, nullptr, C_SZ, C_SZ, C_SZ, L_SZ, CL, CL, LL, 0, alpha);

    // 7. softmax -> bf16 split probs [B,L,L]
    softmax_split<<<B_SZ * L_SZ, 256>>>(scores, at_hi, at_lo);

    // 8. ht[i,c] = at[i,:]·v[c,:]  (M=L, N=C, K=L, no bias)
    mma_gemm<2><<<dim3(4, 8, 16), 256, SMEM_GEMM_BYTES>>>(
        at_hi, at_lo, v_hi, v_lo, nullptr, nullptr,
        ht_hi, ht_lo, L_SZ, L_SZ, L_SZ, C_SZ, LL, CL, CL, 0, 0.f);

    // 9. out[c,l] = Wp[c,:]·ht[l,:] + bp + x[c,l]  (plain Wp/bp, residual)
    mma_gemm<4><<<dim3(8, 4, 16), 256, SMEM_GEMM_BYTES>>>(
        w_hi + 3 * CC, w_lo + 3 * CC, ht_hi, ht_lo, bp, x,
        out, nullptr, C_SZ, C_SZ, C_SZ, L_SZ, 0, CL, CL, CL, 0.f);
}

// round 10
// speedup vs baseline: 3.9128x; 1.3967x over previous
#include <cuda_runtime.h>
#include <cuda_bf16.h>
#include <cstdint>
#include <math.h>

#define B_SZ 16
#define C_SZ 512
#define L_SZ 1024
#define BN_EPS 1e-5f
#define CL (C_SZ * L_SZ)        // 524288
#define LL (L_SZ * L_SZ)        // 1048576
#define CC (C_SZ * C_SZ)        // 262144

// ======================= scratch (static device globals) =======================
__device__ float g_mean[C_SZ];
__device__ float g_rstd[C_SZ];
__device__ __nv_bfloat16 g_xt_hi[B_SZ * CL];   // RAW x, transposed [B,L,C], split
__device__ __nv_bfloat16 g_xt_lo[B_SZ * CL];
__device__ __nv_bfloat16 g_w_hi[4 * CC];       // Wq',Wk',Wv' (BN-folded), Wp (plain)
__device__ __nv_bfloat16 g_w_lo[4 * CC];
__device__ float g_bfold[3 * C_SZ];            // folded biases for q,k,v
__device__ __nv_bfloat16 g_qt_hi[B_SZ * CL];   // q transposed [B,L,C] (hi only)
__device__ __nv_bfloat16 g_kt_hi[B_SZ * CL];
__device__ __nv_bfloat16 g_v_hi[B_SZ * CL];    // v natural [B,C,L] (hi only)
__device__ float g_scores[B_SZ * LL];
__device__ __nv_bfloat16 g_at_hi[B_SZ * LL];   // attn probs [B,L,L] (hi only)
__device__ __nv_bfloat16 g_ht_hi[B_SZ * CL];   // h_ transposed [B,L,C], split
__device__ __nv_bfloat16 g_ht_lo[B_SZ * CL];

// ======================= helpers =======================
__device__ __forceinline__ uint32_t smem_to_u32(const void* p) {
    uint32_t a;
    asm("{ .reg .u64 t; cvta.to.shared.u64 t, %1; cvt.u32.u64 %0, t; }" : "=r"(a) : "l"(p));
    return a;
}
#define SWZ128(off) ((off) ^ (((off) >> 3) & 0x70))

__device__ __forceinline__ void cp16(uint32_t dst, const void* src) {
    asm volatile("cp.async.cg.shared.global [%0], [%1], 16;" :: "r"(dst), "l"(src));
}
__device__ __forceinline__ void cp_commit() {
    asm volatile("cp.async.commit_group;");
}
template <int N>
__device__ __forceinline__ void cp_wait() {
    asm volatile("cp.async.wait_group %0;" :: "n"(N));
}
__device__ __forceinline__ void ldsm4(uint32_t* r, uint32_t addr) {
    asm volatile("ldmatrix.sync.aligned.m8n8.x4.shared.b16 {%0,%1,%2,%3}, [%4];"
                 : "=r"(r[0]), "=r"(r[1]), "=r"(r[2]), "=r"(r[3]) : "r"(addr));
}
__device__ __forceinline__ void mma16816(float* c, const uint32_t* a, uint32_t b0, uint32_t b1) {
    asm volatile(
        "mma.sync.aligned.m16n8k16.row.col.f32.bf16.bf16.f32 "
        "{%0,%1,%2,%3}, {%4,%5,%6,%7}, {%8,%9}, {%0,%1,%2,%3};"
        : "+f"(c[0]), "+f"(c[1]), "+f"(c[2]), "+f"(c[3])
        : "r"(a[0]), "r"(a[1]), "r"(a[2]), "r"(a[3]), "r"(b0), "r"(b1));
}
__device__ __forceinline__ void split_bf16(float v, __nv_bfloat16& h, __nv_bfloat16& l) {
    h = __float2bfloat16(v);
    l = __float2bfloat16(v - __bfloat162float(h));
}
__device__ __forceinline__ uint32_t pack_bf16(__nv_bfloat16 a, __nv_bfloat16 b) {
    return (uint32_t)__bfloat16_as_ushort(a) | ((uint32_t)__bfloat16_as_ushort(b) << 16);
}

// ======================= BatchNorm stats =======================
__global__ __launch_bounds__(256) void bn_stats(const float* __restrict__ x) {
    const int c = blockIdx.x;
    const float* xc = x + (size_t)c * L_SZ;
    float s = 0.f, ss = 0.f;
    for (int idx = threadIdx.x; idx < B_SZ * L_SZ; idx += 256) {
        int b = idx >> 10, l = idx & (L_SZ - 1);
        float v = xc[(size_t)b * CL + l];
        s += v; ss += v * v;
    }
    __shared__ float shs[256], shq[256];
    shs[threadIdx.x] = s; shq[threadIdx.x] = ss;
    __syncthreads();
    for (int o = 128; o > 0; o >>= 1) {
        if (threadIdx.x < o) { shs[threadIdx.x] += shs[threadIdx.x + o]; shq[threadIdx.x] += shq[threadIdx.x + o]; }
        __syncthreads();
    }
    if (threadIdx.x == 0) {
        const float inv_n = 1.f / (float)(B_SZ * L_SZ);
        float m = shs[0] * inv_n;
        float var = shq[0] * inv_n - m * m;
        g_mean[c] = m;
        g_rstd[c] = rsqrtf(var + BN_EPS);
    }
}

// ======================= x -> RAW transposed, bf16-split =======================
__global__ __launch_bounds__(256) void transpose_split(
    const float* __restrict__ x,
    __nv_bfloat16* __restrict__ th, __nv_bfloat16* __restrict__ tl) {
    __shared__ float tile[32][33];
    const int b = blockIdx.z, c0 = blockIdx.y << 5, l0 = blockIdx.x << 5;
    const int tx = threadIdx.x, ty = threadIdx.y;   // (32, 8)
    const float* xb = x + ((size_t)b * C_SZ + c0) * L_SZ + l0;
#pragma unroll
    for (int r = ty; r < 32; r += 8)
        tile[r][tx] = xb[(size_t)r * L_SZ + tx];
    __syncthreads();
    size_t ob = ((size_t)b * L_SZ + l0) * C_SZ + c0;
#pragma unroll
    for (int r = ty; r < 32; r += 8) {
        float v = tile[tx][r];
        __nv_bfloat16 h, l; split_bf16(v, h, l);
        th[ob + (size_t)r * C_SZ + tx] = h;
        tl[ob + (size_t)r * C_SZ + tx] = l;
    }
}

// ======================= all 4 weights: (optional BN fold) + split, one launch =======================
__global__ __launch_bounds__(256) void w_split_all(
    const float* __restrict__ Wq, const float* __restrict__ Wk,
    const float* __restrict__ Wv, const float* __restrict__ Wp,
    const float* __restrict__ gamma,
    __nv_bfloat16* __restrict__ wh, __nv_bfloat16* __restrict__ wl) {
    int i = blockIdx.x * 256 + threadIdx.x;
    int which = i >> 18;                 // i / CC
    int j = i & (CC - 1);
    const float* W = which == 0 ? Wq : which == 1 ? Wk : which == 2 ? Wv : Wp;
    float v = W[j];
    if (which < 3) { int c = j & (C_SZ - 1); v *= g_rstd[c] * gamma[c]; }
    __nv_bfloat16 h, l; split_bf16(v, h, l);
    wh[i] = h; wl[i] = l;
}

// folded biases for q,k,v in one launch: b'[o] = b[o] + sum_c W[o,c]*(beta[c]-mean[c]*s[c])
__global__ __launch_bounds__(128) void bias_fold_all(
    const float* __restrict__ Wq, const float* __restrict__ bq,
    const float* __restrict__ Wk, const float* __restrict__ bk,
    const float* __restrict__ Wv, const float* __restrict__ bv,
    const float* __restrict__ gamma, const float* __restrict__ beta,
    float* __restrict__ bout) {
    const int o = blockIdx.x, which = blockIdx.y;
    const float* W = which == 0 ? Wq : which == 1 ? Wk : Wv;
    const float* b = which == 0 ? bq : which == 1 ? bk : bv;
    float acc = 0.f;
    for (int c = threadIdx.x; c < C_SZ; c += 128) {
        float s = g_rstd[c] * gamma[c];
        float t = beta[c] - g_mean[c] * s;
        acc += W[o * C_SZ + c] * t;
    }
    __shared__ float sh[128];
    sh[threadIdx.x] = acc;
    __syncthreads();
    for (int o2 = 64; o2 > 0; o2 >>= 1) {
        if (threadIdx.x < o2) sh[threadIdx.x] += sh[threadIdx.x + o2];
        __syncthreads();
    }
    if (threadIdx.x == 0) bout[which * C_SZ + o] = b[o] + sh[0];
}

// ======================= mma.sync GEMM (SW128 + ldmatrix.x4) =======================
// D[m,n] = sum_k A[m,k]*B[n,k], K-major operands.
// SPLIT=1: hi/lo 3-term split (4 smem tiles/stage); SPLIT=0: hi-only (2 tiles/stage, occ 2).
// WLO=1: bf16 epilogues also write the lo plane.
// EPI 0: bf16 out, bias per-n; EPI 1: bf16 out, bias per-m; EPI 2: bf16 out, no bias
// EPI 3: fp32 * alpha out;     EPI 4: fp32 + bias per-m + residual out
template <int EPI, int SPLIT, int WLO>
__global__ void __launch_bounds__(256, SPLIT ? 1 : 2) mma_gemm(
    const __nv_bfloat16* __restrict__ Ahi, const __nv_bfloat16* __restrict__ Alo,
    const __nv_bfloat16* __restrict__ Bhi, const __nv_bfloat16* __restrict__ Blo,
    const float* __restrict__ bias, const float* __restrict__ res,
    void* outA, void* outB,
    int K, int ldA, int ldB, int ldO,
    long sA, long sB, long sO, long sRes, float alpha) {
    constexpr uint32_t NTILE = SPLIT ? 4 : 2;
    constexpr uint32_t STAGE = NTILE * 16384u;
    constexpr uint32_t BOFF = SPLIT ? 32768u : 16384u;   // Bhi tile offset in stage
    extern __shared__ char smem[];
    const uint32_t sb = smem_to_u32(smem);
    const int tid = threadIdx.x, lane = tid & 31, wid = tid >> 5;
    const int bz = blockIdx.z;
    const int m0 = blockIdx.y << 7, n0 = blockIdx.x << 7;

    const char* gAh = (const char*)(Ahi + (size_t)bz * sA);
    const char* gAl = (const char*)(Alo + (size_t)bz * sA);
    const char* gBh = (const char*)(Bhi + (size_t)bz * sB);
    const char* gBl = (const char*)(Blo + (size_t)bz * sB);
    const size_t ldA2 = (size_t)ldA * 2, ldB2 = (size_t)ldB * 2;

    const int wm = (wid & 3) * 32;     // warp m offset
    const int wn = (wid >> 2) * 64;    // warp n offset

    float acc[2][8][4];
#pragma unroll
    for (int a = 0; a < 2; a++)
#pragma unroll
        for (int b = 0; b < 8; b++)
#pragma unroll
            for (int c = 0; c < 4; c++) acc[a][b][c] = 0.f;

    const int nst = K >> 6;

    auto prefetch = [&](int s) {
        uint32_t st = sb + (uint32_t)(s & 1) * STAGE;
        size_t kb = (size_t)s * 128;   // 64 bf16 = 128B along K
#pragma unroll
        for (int i = 0; i < 4; i++) {
            int idx = tid + (i << 8);
            int row = idx >> 3, ch = idx & 7;
            uint32_t doff = SWZ128((uint32_t)row * 128u + (uint32_t)ch * 16u);
            size_t aoff = (size_t)(m0 + row) * ldA2 + kb + (size_t)ch * 16;
            size_t boff = (size_t)(n0 + row) * ldB2 + kb + (size_t)ch * 16;
            cp16(st + doff,         gAh + aoff);
            cp16(st + BOFF + doff,  gBh + boff);
            if (SPLIT) {
                cp16(st + 16384u + doff, gAl + aoff);
                cp16(st + 49152u + doff, gBl + boff);
            }
        }
        cp_commit();
    };

    prefetch(0);

    // ldmatrix lane address components (canonical x4 patterns)
    const int a_row  = (lane & 7) + ((lane >> 3) & 1) * 8;
    const int a_koff = (lane >> 4) * 16;                     // bytes
    const int b_row  = (lane & 7) + (lane >> 4) * 8;
    const int b_koff = ((lane >> 3) & 1) * 16;

    for (int s = 0; s < nst; s++) {
        if (s + 1 < nst) { prefetch(s + 1); cp_wait<1>(); }
        else             { cp_wait<0>(); }
        __syncthreads();
        const uint32_t st = sb + (uint32_t)(s & 1) * STAGE;
#pragma unroll
        for (int kk = 0; kk < 4; kk++) {
            uint32_t ah[2][4], al_[2][4], bh[4][4], bl_[4][4];
#pragma unroll
            for (int mi = 0; mi < 2; mi++) {
                uint32_t off = SWZ128((uint32_t)((wm + mi * 16 + a_row) * 128 + kk * 32 + a_koff));
                ldsm4(ah[mi], st + off);
                if (SPLIT) ldsm4(al_[mi], st + 16384u + off);
            }
#pragma unroll
            for (int ni = 0; ni < 4; ni++) {
                uint32_t off = SWZ128((uint32_t)((wn + ni * 16 + b_row) * 128 + kk * 32 + b_koff));
                ldsm4(bh[ni], st + BOFF + off);
                if (SPLIT) ldsm4(bl_[ni], st + 49152u + off);
            }
#pragma unroll
            for (int mi = 0; mi < 2; mi++)
#pragma unroll
                for (int n8 = 0; n8 < 8; n8++) {
                    int ni = n8 >> 1, hf = (n8 & 1) * 2;
                    mma16816(acc[mi][n8], ah[mi], bh[ni][hf], bh[ni][hf + 1]);
                    if (SPLIT) {
                        mma16816(acc[mi][n8], ah[mi],  bl_[ni][hf], bl_[ni][hf + 1]);
                        mma16816(acc[mi][n8], al_[mi], bh[ni][hf],  bh[ni][hf + 1]);
                    }
                }
        }
        __syncthreads();
    }

    // ---------------- epilogue ----------------
#pragma unroll
    for (int mi = 0; mi < 2; mi++) {
        const int r0 = m0 + wm + mi * 16 + (lane >> 2);
        const int r1 = r0 + 8;
#pragma unroll
        for (int n8 = 0; n8 < 8; n8++) {
            const int col = n0 + wn + n8 * 8 + 2 * (lane & 3);
            float* a4 = acc[mi][n8];
            if (EPI == 3) {
                float* o = (float*)outA + (size_t)bz * sO;
                float2 v0 = make_float2(a4[0] * alpha, a4[1] * alpha);
                float2 v1 = make_float2(a4[2] * alpha, a4[3] * alpha);
                *(float2*)(o + (size_t)r0 * ldO + col) = v0;
                *(float2*)(o + (size_t)r1 * ldO + col) = v1;
            } else if (EPI == 4) {
                float* o = (float*)outA + (size_t)bz * sO;
                const float* rp = res + (size_t)bz * sRes;
                float bi0 = bias[r0], bi1 = bias[r1];
                float2 q0 = *(const float2*)(rp + (size_t)r0 * ldO + col);
                float2 q1 = *(const float2*)(rp + (size_t)r1 * ldO + col);
                float2 v0 = make_float2(a4[0] + bi0 + q0.x, a4[1] + bi0 + q0.y);
                float2 v1 = make_float2(a4[2] + bi1 + q1.x, a4[3] + bi1 + q1.y);
                *(float2*)(o + (size_t)r0 * ldO + col) = v0;
                *(float2*)(o + (size_t)r1 * ldO + col) = v1;
            } else {
                float b00 = 0.f, b01 = 0.f, b10 = 0.f, b11 = 0.f;
                if (EPI == 0) { float bn0 = bias[col], bn1 = bias[col + 1]; b00 = bn0; b01 = bn1; b10 = bn0; b11 = bn1; }
                if (EPI == 1) { float bm0 = bias[r0], bm1 = bias[r1]; b00 = bm0; b01 = bm0; b10 = bm1; b11 = bm1; }
                __nv_bfloat16 h0, l0, h1, l1, h2, l2, h3, l3;
                split_bf16(a4[0] + b00, h0, l0);
                split_bf16(a4[1] + b01, h1, l1);
                split_bf16(a4[2] + b10, h2, l2);
                split_bf16(a4[3] + b11, h3, l3);
                __nv_bfloat16* oh = (__nv_bfloat16*)outA + (size_t)bz * sO;
                *(uint32_t*)(oh + (size_t)r0 * ldO + col) = pack_bf16(h0, h1);
                *(uint32_t*)(oh + (size_t)r1 * ldO + col) = pack_bf16(h2, h3);
                if (WLO) {
                    __nv_bfloat16* ol = (__nv_bfloat16*)outB + (size_t)bz * sO;
                    *(uint32_t*)(ol + (size_t)r0 * ldO + col) = pack_bf16(l0, l1);
                    *(uint32_t*)(ol + (size_t)r1 * ldO + col) = pack_bf16(l2, l3);
                }
            }
        }
    }
}

// ======================= softmax -> bf16 hi probs =======================
__global__ __launch_bounds__(256) void softmax_hi(
    const float* __restrict__ sc, __nv_bfloat16* __restrict__ ah) {
    const size_t row = blockIdx.x;
    const float4* p4 = (const float4*)(sc + row * L_SZ);
    const int t = threadIdx.x;
    float4 v = p4[t];
    __shared__ float sh[256];
    float mx = fmaxf(fmaxf(v.x, v.y), fmaxf(v.z, v.w));
    sh[t] = mx; __syncthreads();
    for (int o = 128; o > 0; o >>= 1) {
        if (t < o) sh[t] = fmaxf(sh[t], sh[t + o]);
        __syncthreads();
    }
    mx = sh[0]; __syncthreads();
    v.x = expf(v.x - mx); v.y = expf(v.y - mx);
    v.z = expf(v.z - mx); v.w = expf(v.w - mx);
    sh[t] = v.x + v.y + v.z + v.w; __syncthreads();
    for (int o = 128; o > 0; o >>= 1) {
        if (t < o) sh[t] += sh[t + o];
        __syncthreads();
    }
    float inv = 1.f / sh[0];
    ((uint2*)(ah + row * L_SZ))[t] = make_uint2(
        pack_bf16(__float2bfloat16(v.x * inv), __float2bfloat16(v.y * inv)),
        pack_bf16(__float2bfloat16(v.z * inv), __float2bfloat16(v.w * inv)));
}

// ======================= launch =======================
extern "C" void kernel_launch(void* const* d_in, const int* in_sizes, int n_in,
                              void* d_out, int out_size) {
    const float* x     = (const float*)d_in[0];
    const float* gamma = (const float*)d_in[1];
    const float* beta  = (const float*)d_in[2];
    const float* Wq = (const float*)d_in[3];  const float* bq = (const float*)d_in[4];
    const float* Wk = (const float*)d_in[5];  const float* bk = (const float*)d_in[6];
    const float* Wv = (const float*)d_in[7];  const float* bv = (const float*)d_in[8];
    const float* Wp = (const float*)d_in[9];  const float* bp = (const float*)d_in[10];
    float* out = (float*)d_out;

    __nv_bfloat16 *xt_hi, *xt_lo, *w_hi, *w_lo, *qt_hi, *kt_hi, *v_hi, *at_hi, *ht_hi, *ht_lo;
    float *scores, *bfold;
    cudaGetSymbolAddress((void**)&xt_hi, g_xt_hi);
    cudaGetSymbolAddress((void**)&xt_lo, g_xt_lo);
    cudaGetSymbolAddress((void**)&w_hi, g_w_hi);
    cudaGetSymbolAddress((void**)&w_lo, g_w_lo);
    cudaGetSymbolAddress((void**)&bfold, g_bfold);
    cudaGetSymbolAddress((void**)&qt_hi, g_qt_hi);
    cudaGetSymbolAddress((void**)&kt_hi, g_kt_hi);
    cudaGetSymbolAddress((void**)&v_hi, g_v_hi);
    cudaGetSymbolAddress((void**)&scores, g_scores);
    cudaGetSymbolAddress((void**)&at_hi, g_at_hi);
    cudaGetSymbolAddress((void**)&ht_hi, g_ht_hi);
    cudaGetSymbolAddress((void**)&ht_lo, g_ht_lo);

    cudaFuncSetAttribute(mma_gemm<0, 1, 0>, cudaFuncAttributeMaxDynamicSharedMemorySize, 131072);
    cudaFuncSetAttribute(mma_gemm<1, 1, 0>, cudaFuncAttributeMaxDynamicSharedMemorySize, 131072);
    cudaFuncSetAttribute(mma_gemm<4, 1, 0>, cudaFuncAttributeMaxDynamicSharedMemorySize, 131072);
    cudaFuncSetAttribute(mma_gemm<3, 0, 0>, cudaFuncAttributeMaxDynamicSharedMemorySize, 65536);
    cudaFuncSetAttribute(mma_gemm<2, 0, 1>, cudaFuncAttributeMaxDynamicSharedMemorySize, 65536);

    // 1. BN stats (feeds the weight/bias folds only)
    bn_stats<<<C_SZ, 256>>>(x);
    // 2. raw x -> transposed bf16 split [B,L,C]
    transpose_split<<<dim3(32, 16, 16), dim3(32, 8)>>>(x, xt_hi, xt_lo);
    // 3. all weights split (BN folded into Wq/Wk/Wv), folded biases — 2 launches
    w_split_all<<<4 * CC / 256, 256>>>(Wq, Wk, Wv, Wp, gamma, w_hi, w_lo);
    bias_fold_all<<<dim3(C_SZ, 3), 128>>>(Wq, bq, Wk, bk, Wv, bv, gamma, beta, bfold);

    // 4. qt[l,c] = xt[l,:]·Wq'[c,:] + bq'  (split, hi out only)
    mma_gemm<0, 1, 0><<<dim3(4, 8, 16), 256, 131072>>>(
        xt_hi, xt_lo, w_hi + 0 * CC, w_lo + 0 * CC, bfold + 0 * C_SZ, nullptr,
        qt_hi, nullptr, C_SZ, C_SZ, C_SZ, C_SZ, CL, 0, CL, 0, 0.f);
    mma_gemm<0, 1, 0><<<dim3(4, 8, 16), 256, 131072>>>(
        xt_hi, xt_lo, w_hi + 1 * CC, w_lo + 1 * CC, bfold + 1 * C_SZ, nullptr,
        kt_hi, nullptr, C_SZ, C_SZ, C_SZ, C_SZ, CL, 0, CL, 0, 0.f);
    // 5. v[c,l] (split, hi out only)
    mma_gemm<1, 1, 0><<<dim3(8, 4, 16), 256, 131072>>>(
        w_hi + 2 * CC, w_lo + 2 * CC, xt_hi, xt_lo, bfold + 2 * C_SZ, nullptr,
        v_hi, nullptr, C_SZ, C_SZ, C_SZ, L_SZ, 0, CL, CL, 0, 0.f);

    // 6. scores = alpha * qt·kt^T  (hi-only MMA)
    const float alpha = 1.f / sqrtf((float)C_SZ);
    mma_gemm<3, 0, 0><<<dim3(8, 8, 16), 256, 65536>>>(
        qt_hi, qt_hi, kt_hi, kt_hi, nullptr, nullptr,
        scores, nullptr, C_SZ, C_SZ, C_SZ, L_SZ, CL, CL, LL, 0, alpha);

    // 7. softmax -> bf16 hi probs
    softmax_hi<<<B_SZ * L_SZ, 256>>>(scores, at_hi);

    // 8. ht[i,c] = at[i,:]·v[c,:]  (hi-only MMA, split output for proj)
    mma_gemm<2, 0, 1><<<dim3(4, 8, 16), 256, 65536>>>(
        at_hi, at_hi, v_hi, v_hi, nullptr, nullptr,
        ht_hi, ht_lo, L_SZ, L_SZ, L_SZ, C_SZ, LL, CL, CL, 0, 0.f);

    // 9. out[c,l] = Wp[c,:]·ht[l,:] + bp + x[c,l]  (split, fp32 + residual)
    mma_gemm<4, 1, 0><<<dim3(8, 4, 16), 256, 131072>>>(
        w_hi + 3 * CC, w_lo + 3 * CC, ht_hi, ht_lo, bp, x,
        out, nullptr, C_SZ, C_SZ, C_SZ, L_SZ, 0, CL, CL, CL, 0.f);
}

// round 11
// speedup vs baseline: 6.0595x; 1.5486x over previous
#include <cuda_runtime.h>
#include <cuda_bf16.h>
#include <cstdint>
#include <math.h>

#define B_SZ 16
#define C_SZ 512
#define L_SZ 1024
#define BN_EPS 1e-5f
#define CL (C_SZ * L_SZ)        // 524288
#define LL (L_SZ * L_SZ)        // 1048576
#define CC (C_SZ * C_SZ)        // 262144

// ======================= scratch (static device globals) =======================
__device__ float g_mean[C_SZ];
__device__ float g_rstd[C_SZ];
__device__ __nv_bfloat16 g_xt[B_SZ * CL];    // RAW x, transposed [B,L,C]
__device__ __nv_bfloat16 g_w[4 * CC];        // Wq',Wk',Wv' (BN-folded), Wp (plain)
__device__ float g_bfold[3 * C_SZ];          // folded biases for q,k,v
__device__ __nv_bfloat16 g_qt[B_SZ * CL];    // q transposed [B,L,C]
__device__ __nv_bfloat16 g_kt[B_SZ * CL];
__device__ __nv_bfloat16 g_v[B_SZ * CL];     // v natural [B,C,L]
__device__ float g_scores[B_SZ * LL];
__device__ __nv_bfloat16 g_at[B_SZ * LL];    // attn probs [B,L,L]
__device__ __nv_bfloat16 g_ht[B_SZ * CL];    // h_ transposed [B,L,C]

// ======================= helpers =======================
__device__ __forceinline__ uint32_t smem_to_u32(const void* p) {
    uint32_t a;
    asm("{ .reg .u64 t; cvta.to.shared.u64 t, %1; cvt.u32.u64 %0, t; }" : "=r"(a) : "l"(p));
    return a;
}
#define SWZ128(off) ((off) ^ (((off) >> 3) & 0x70))

__device__ __forceinline__ void cp16(uint32_t dst, const void* src) {
    asm volatile("cp.async.cg.shared.global [%0], [%1], 16;" :: "r"(dst), "l"(src));
}
__device__ __forceinline__ void cp_commit() {
    asm volatile("cp.async.commit_group;");
}
template <int N>
__device__ __forceinline__ void cp_wait() {
    asm volatile("cp.async.wait_group %0;" :: "n"(N));
}
__device__ __forceinline__ void ldsm4(uint32_t* r, uint32_t addr) {
    asm volatile("ldmatrix.sync.aligned.m8n8.x4.shared.b16 {%0,%1,%2,%3}, [%4];"
                 : "=r"(r[0]), "=r"(r[1]), "=r"(r[2]), "=r"(r[3]) : "r"(addr));
}
__device__ __forceinline__ void mma16816(float* c, const uint32_t* a, uint32_t b0, uint32_t b1) {
    asm volatile(
        "mma.sync.aligned.m16n8k16.row.col.f32.bf16.bf16.f32 "
        "{%0,%1,%2,%3}, {%4,%5,%6,%7}, {%8,%9}, {%0,%1,%2,%3};"
        : "+f"(c[0]), "+f"(c[1]), "+f"(c[2]), "+f"(c[3])
        : "r"(a[0]), "r"(a[1]), "r"(a[2]), "r"(a[3]), "r"(b0), "r"(b1));
}
__device__ __forceinline__ uint32_t pack_bf16(__nv_bfloat16 a, __nv_bfloat16 b) {
    return (uint32_t)__bfloat16_as_ushort(a) | ((uint32_t)__bfloat16_as_ushort(b) << 16);
}

// ======================= BatchNorm stats =======================
__global__ __launch_bounds__(256) void bn_stats(const float* __restrict__ x) {
    const int c = blockIdx.x;
    const float* xc = x + (size_t)c * L_SZ;
    float s = 0.f, ss = 0.f;
    for (int idx = threadIdx.x; idx < B_SZ * L_SZ; idx += 256) {
        int b = idx >> 10, l = idx & (L_SZ - 1);
        float v = xc[(size_t)b * CL + l];
        s += v; ss += v * v;
    }
    __shared__ float shs[256], shq[256];
    shs[threadIdx.x] = s; shq[threadIdx.x] = ss;
    __syncthreads();
    for (int o = 128; o > 0; o >>= 1) {
        if (threadIdx.x < o) { shs[threadIdx.x] += shs[threadIdx.x + o]; shq[threadIdx.x] += shq[threadIdx.x + o]; }
        __syncthreads();
    }
    if (threadIdx.x == 0) {
        const float inv_n = 1.f / (float)(B_SZ * L_SZ);
        float m = shs[0] * inv_n;
        float var = shq[0] * inv_n - m * m;
        g_mean[c] = m;
        g_rstd[c] = rsqrtf(var + BN_EPS);
    }
}

// ======================= x -> RAW transposed bf16 =======================
__global__ __launch_bounds__(256) void transpose_bf16(
    const float* __restrict__ x, __nv_bfloat16* __restrict__ th) {
    __shared__ float tile[32][33];
    const int b = blockIdx.z, c0 = blockIdx.y << 5, l0 = blockIdx.x << 5;
    const int tx = threadIdx.x, ty = threadIdx.y;   // (32, 8)
    const float* xb = x + ((size_t)b * C_SZ + c0) * L_SZ + l0;
#pragma unroll
    for (int r = ty; r < 32; r += 8)
        tile[r][tx] = xb[(size_t)r * L_SZ + tx];
    __syncthreads();
    size_t ob = ((size_t)b * L_SZ + l0) * C_SZ + c0;
#pragma unroll
    for (int r = ty; r < 32; r += 8)
        th[ob + (size_t)r * C_SZ + tx] = __float2bfloat16(tile[tx][r]);
}

// ======================= all 4 weights: (optional BN fold) -> bf16, one launch =======================
__global__ __launch_bounds__(256) void w_fold_bf16(
    const float* __restrict__ Wq, const float* __restrict__ Wk,
    const float* __restrict__ Wv, const float* __restrict__ Wp,
    const float* __restrict__ gamma, __nv_bfloat16* __restrict__ wh) {
    int i = blockIdx.x * 256 + threadIdx.x;
    int which = i >> 18;                 // i / CC
    int j = i & (CC - 1);
    const float* W = which == 0 ? Wq : which == 1 ? Wk : which == 2 ? Wv : Wp;
    float v = W[j];
    if (which < 3) { int c = j & (C_SZ - 1); v *= g_rstd[c] * gamma[c]; }
    wh[i] = __float2bfloat16(v);
}

// folded biases for q,k,v: b'[o] = b[o] + sum_c W[o,c]*(beta[c]-mean[c]*s[c])
__global__ __launch_bounds__(128) void bias_fold_all(
    const float* __restrict__ Wq, const float* __restrict__ bq,
    const float* __restrict__ Wk, const float* __restrict__ bk,
    const float* __restrict__ Wv, const float* __restrict__ bv,
    const float* __restrict__ gamma, const float* __restrict__ beta,
    float* __restrict__ bout) {
    const int o = blockIdx.x, which = blockIdx.y;
    const float* W = which == 0 ? Wq : which == 1 ? Wk : Wv;
    const float* b = which == 0 ? bq : which == 1 ? bk : bv;
    float acc = 0.f;
    for (int c = threadIdx.x; c < C_SZ; c += 128) {
        float s = g_rstd[c] * gamma[c];
        float t = beta[c] - g_mean[c] * s;
        acc += W[o * C_SZ + c] * t;
    }
    __shared__ float sh[128];
    sh[threadIdx.x] = acc;
    __syncthreads();
    for (int o2 = 64; o2 > 0; o2 >>= 1) {
        if (threadIdx.x < o2) sh[threadIdx.x] += sh[threadIdx.x + o2];
        __syncthreads();
    }
    if (threadIdx.x == 0) bout[which * C_SZ + o] = b[o] + sh[0];
}

// ======================= mma.sync bf16 GEMM (SW128 + ldmatrix.x4, hi-only) =======================
// D[m,n] = sum_k A[m,k]*B[n,k], K-major operands. CTA tile 128x128, BK=64,
// double-buffered cp.async (2x32KB stages -> occupancy 2), 8 warps of 32x64.
// EPI 0: bf16 out, bias per-n; EPI 1: bf16 out, bias per-m; EPI 2: bf16 out, no bias
// EPI 3: fp32 * alpha out;     EPI 4: fp32 + bias per-m + residual out
#define STAGE 32768u
#define SMEM_GEMM_BYTES (2 * STAGE)

template <int EPI>
__global__ void __launch_bounds__(256, 2) mma_gemm(
    const __nv_bfloat16* __restrict__ A, const __nv_bfloat16* __restrict__ B,
    const float* __restrict__ bias, const float* __restrict__ res,
    void* outA,
    int K, int ldA, int ldB, int ldO,
    long sA, long sB, long sO, long sRes, float alpha) {
    extern __shared__ char smem[];
    const uint32_t sb = smem_to_u32(smem);
    const int tid = threadIdx.x, lane = tid & 31, wid = tid >> 5;
    const int bz = blockIdx.z;
    const int m0 = blockIdx.y << 7, n0 = blockIdx.x << 7;

    const char* gA = (const char*)(A + (size_t)bz * sA);
    const char* gB = (const char*)(B + (size_t)bz * sB);
    const size_t ldA2 = (size_t)ldA * 2, ldB2 = (size_t)ldB * 2;

    const int wm = (wid & 3) * 32;     // warp m offset
    const int wn = (wid >> 2) * 64;    // warp n offset

    float acc[2][8][4];
#pragma unroll
    for (int a = 0; a < 2; a++)
#pragma unroll
        for (int b = 0; b < 8; b++)
#pragma unroll
            for (int c = 0; c < 4; c++) acc[a][b][c] = 0.f;

    const int nst = K >> 6;

    auto prefetch = [&](int s) {
        uint32_t st = sb + (uint32_t)(s & 1) * STAGE;
        size_t kb = (size_t)s * 128;   // 64 bf16 = 128B along K
#pragma unroll
        for (int i = 0; i < 4; i++) {
            int idx = tid + (i << 8);
            int row = idx >> 3, ch = idx & 7;
            uint32_t doff = SWZ128((uint32_t)row * 128u + (uint32_t)ch * 16u);
            cp16(st + doff,           gA + (size_t)(m0 + row) * ldA2 + kb + (size_t)ch * 16);
            cp16(st + 16384u + doff,  gB + (size_t)(n0 + row) * ldB2 + kb + (size_t)ch * 16);
        }
        cp_commit();
    };

    prefetch(0);

    // ldmatrix lane address components (canonical x4 patterns)
    const int a_row  = (lane & 7) + ((lane >> 3) & 1) * 8;
    const int a_koff = (lane >> 4) * 16;                     // bytes
    const int b_row  = (lane & 7) + (lane >> 4) * 8;
    const int b_koff = ((lane >> 3) & 1) * 16;

    for (int s = 0; s < nst; s++) {
        if (s + 1 < nst) { prefetch(s + 1); cp_wait<1>(); }
        else             { cp_wait<0>(); }
        __syncthreads();
        const uint32_t st = sb + (uint32_t)(s & 1) * STAGE;
#pragma unroll
        for (int kk = 0; kk < 4; kk++) {
            uint32_t ah[2][4], bh[4][4];
#pragma unroll
            for (int mi = 0; mi < 2; mi++) {
                uint32_t off = SWZ128((uint32_t)((wm + mi * 16 + a_row) * 128 + kk * 32 + a_koff));
                ldsm4(ah[mi], st + off);
            }
#pragma unroll
            for (int ni = 0; ni < 4; ni++) {
                uint32_t off = SWZ128((uint32_t)((wn + ni * 16 + b_row) * 128 + kk * 32 + b_koff));
                ldsm4(bh[ni], st + 16384u + off);
            }
#pragma unroll
            for (int mi = 0; mi < 2; mi++)
#pragma unroll
                for (int n8 = 0; n8 < 8; n8++) {
                    int ni = n8 >> 1, hf = (n8 & 1) * 2;
                    mma16816(acc[mi][n8], ah[mi], bh[ni][hf], bh[ni][hf + 1]);
                }
        }
        __syncthreads();
    }

    // ---------------- epilogue ----------------
#pragma unroll
    for (int mi = 0; mi < 2; mi++) {
        const int r0 = m0 + wm + mi * 16 + (lane >> 2);
        const int r1 = r0 + 8;
#pragma unroll
        for (int n8 = 0; n8 < 8; n8++) {
            const int col = n0 + wn + n8 * 8 + 2 * (lane & 3);
            float* a4 = acc[mi][n8];
            if (EPI == 3) {
                float* o = (float*)outA + (size_t)bz * sO;
                *(float2*)(o + (size_t)r0 * ldO + col) = make_float2(a4[0] * alpha, a4[1] * alpha);
                *(float2*)(o + (size_t)r1 * ldO + col) = make_float2(a4[2] * alpha, a4[3] * alpha);
            } else if (EPI == 4) {
                float* o = (float*)outA + (size_t)bz * sO;
                const float* rp = res + (size_t)bz * sRes;
                float bi0 = bias[r0], bi1 = bias[r1];
                float2 q0 = *(const float2*)(rp + (size_t)r0 * ldO + col);
                float2 q1 = *(const float2*)(rp + (size_t)r1 * ldO + col);
                *(float2*)(o + (size_t)r0 * ldO + col) = make_float2(a4[0] + bi0 + q0.x, a4[1] + bi0 + q0.y);
                *(float2*)(o + (size_t)r1 * ldO + col) = make_float2(a4[2] + bi1 + q1.x, a4[3] + bi1 + q1.y);
            } else {
                float b00 = 0.f, b01 = 0.f, b10 = 0.f, b11 = 0.f;
                if (EPI == 0) { float bn0 = bias[col], bn1 = bias[col + 1]; b00 = bn0; b01 = bn1; b10 = bn0; b11 = bn1; }
                if (EPI == 1) { float bm0 = bias[r0], bm1 = bias[r1]; b00 = bm0; b01 = bm0; b10 = bm1; b11 = bm1; }
                __nv_bfloat16* oh = (__nv_bfloat16*)outA + (size_t)bz * sO;
                *(uint32_t*)(oh + (size_t)r0 * ldO + col) =
                    pack_bf16(__float2bfloat16(a4[0] + b00), __float2bfloat16(a4[1] + b01));
                *(uint32_t*)(oh + (size_t)r1 * ldO + col) =
                    pack_bf16(__float2bfloat16(a4[2] + b10), __float2bfloat16(a4[3] + b11));
            }
        }
    }
}

// ======================= softmax -> bf16 probs =======================
__global__ __launch_bounds__(256) void softmax_hi(
    const float* __restrict__ sc, __nv_bfloat16* __restrict__ ah) {
    const size_t row = blockIdx.x;
    const float4* p4 = (const float4*)(sc + row * L_SZ);
    const int t = threadIdx.x;
    float4 v = p4[t];
    __shared__ float sh[256];
    float mx = fmaxf(fmaxf(v.x, v.y), fmaxf(v.z, v.w));
    sh[t] = mx; __syncthreads();
    for (int o = 128; o > 0; o >>= 1) {
        if (t < o) sh[t] = fmaxf(sh[t], sh[t + o]);
        __syncthreads();
    }
    mx = sh[0]; __syncthreads();
    v.x = expf(v.x - mx); v.y = expf(v.y - mx);
    v.z = expf(v.z - mx); v.w = expf(v.w - mx);
    sh[t] = v.x + v.y + v.z + v.w; __syncthreads();
    for (int o = 128; o > 0; o >>= 1) {
        if (t < o) sh[t] += sh[t + o];
        __syncthreads();
    }
    float inv = 1.f / sh[0];
    ((uint2*)(ah + row * L_SZ))[t] = make_uint2(
        pack_bf16(__float2bfloat16(v.x * inv), __float2bfloat16(v.y * inv)),
        pack_bf16(__float2bfloat16(v.z * inv), __float2bfloat16(v.w * inv)));
}

// ======================= launch =======================
extern "C" void kernel_launch(void* const* d_in, const int* in_sizes, int n_in,
                              void* d_out, int out_size) {
    const float* x     = (const float*)d_in[0];
    const float* gamma = (const float*)d_in[1];
    const float* beta  = (const float*)d_in[2];
    const float* Wq = (const float*)d_in[3];  const float* bq = (const float*)d_in[4];
    const float* Wk = (const float*)d_in[5];  const float* bk = (const float*)d_in[6];
    const float* Wv = (const float*)d_in[7];  const float* bv = (const float*)d_in[8];
    const float* Wp = (const float*)d_in[9];  const float* bp = (const float*)d_in[10];
    float* out = (float*)d_out;

    __nv_bfloat16 *xt, *w, *qt, *kt, *v, *at, *ht;
    float *scores, *bfold;
    cudaGetSymbolAddress((void**)&xt, g_xt);
    cudaGetSymbolAddress((void**)&w, g_w);
    cudaGetSymbolAddress((void**)&bfold, g_bfold);
    cudaGetSymbolAddress((void**)&qt, g_qt);
    cudaGetSymbolAddress((void**)&kt, g_kt);
    cudaGetSymbolAddress((void**)&v, g_v);
    cudaGetSymbolAddress((void**)&scores, g_scores);
    cudaGetSymbolAddress((void**)&at, g_at);
    cudaGetSymbolAddress((void**)&ht, g_ht);

    cudaFuncSetAttribute(mma_gemm<0>, cudaFuncAttributeMaxDynamicSharedMemorySize, SMEM_GEMM_BYTES);
    cudaFuncSetAttribute(mma_gemm<1>, cudaFuncAttributeMaxDynamicSharedMemorySize, SMEM_GEMM_BYTES);
    cudaFuncSetAttribute(mma_gemm<2>, cudaFuncAttributeMaxDynamicSharedMemorySize, SMEM_GEMM_BYTES);
    cudaFuncSetAttribute(mma_gemm<3>, cudaFuncAttributeMaxDynamicSharedMemorySize, SMEM_GEMM_BYTES);
    cudaFuncSetAttribute(mma_gemm<4>, cudaFuncAttributeMaxDynamicSharedMemorySize, SMEM_GEMM_BYTES);

    // 1. BN stats (feeds the weight/bias folds only)
    bn_stats<<<C_SZ, 256>>>(x);
    // 2. raw x -> transposed bf16 [B,L,C]
    transpose_bf16<<<dim3(32, 16, 16), dim3(32, 8)>>>(x, xt);
    // 3. weights (BN folded into Wq/Wk/Wv) + folded biases
    w_fold_bf16<<<4 * CC / 256, 256>>>(Wq, Wk, Wv, Wp, gamma, w);
    bias_fold_all<<<dim3(C_SZ, 3), 128>>>(Wq, bq, Wk, bk, Wv, bv, gamma, beta, bfold);

    // 4. qt[l,c] = xt[l,:]·Wq'[c,:] + bq'   kt likewise
    mma_gemm<0><<<dim3(4, 8, 16), 256, SMEM_GEMM_BYTES>>>(
        xt, w + 0 * CC, bfold + 0 * C_SZ, nullptr, qt,
        C_SZ, C_SZ, C_SZ, C_SZ, CL, 0, CL, 0, 0.f);
    mma_gemm<0><<<dim3(4, 8, 16), 256, SMEM_GEMM_BYTES>>>(
        xt, w + 1 * CC, bfold + 1 * C_SZ, nullptr, kt,
        C_SZ, C_SZ, C_SZ, C_SZ, CL, 0, CL, 0, 0.f);
    // 5. v[c,l] = Wv'[c,:]·xt[l,:] + bv'
    mma_gemm<1><<<dim3(8, 4, 16), 256, SMEM_GEMM_BYTES>>>(
        w + 2 * CC, xt, bfold + 2 * C_SZ, nullptr, v,
        C_SZ, C_SZ, C_SZ, L_SZ, 0, CL, CL, 0, 0.f);

    // 6. scores = alpha * qt·kt^T
    const float alpha = 1.f / sqrtf((float)C_SZ);
    mma_gemm<3><<<dim3(8, 8, 16), 256, SMEM_GEMM_BYTES>>>(
        qt, kt, nullptr, nullptr, scores,
        C_SZ, C_SZ, C_SZ, L_SZ, CL, CL, LL, 0, alpha);

    // 7. softmax -> bf16 probs
    softmax_hi<<<B_SZ * L_SZ, 256>>>(scores, at);

    // 8. ht[i,c] = at[i,:]·v[c,:]
    mma_gemm<2><<<dim3(4, 8, 16), 256, SMEM_GEMM_BYTES>>>(
        at, v, nullptr, nullptr, ht,
        L_SZ, L_SZ, L_SZ, C_SZ, LL, CL, CL, 0, 0.f);

    // 9. out[c,l] = Wp[c,:]·ht[l,:] + bp + x[c,l]
    mma_gemm<4><<<dim3(8, 4, 16), 256, SMEM_GEMM_BYTES>>>(
        w + 3 * CC, ht, bp, x, out,
        C_SZ, C_SZ, C_SZ, L_SZ, 0, CL, CL, CL, 0.f);
}

// round 12
// speedup vs baseline: 6.1951x; 1.0224x over previous
#include <cuda_runtime.h>
#include <cuda_bf16.h>
#include <cstdint>
#include <math.h>

#define B_SZ 16
#define C_SZ 512
#define L_SZ 1024
#define BN_EPS 1e-5f
#define CL (C_SZ * L_SZ)        // 524288
#define LL (L_SZ * L_SZ)        // 1048576
#define CC (C_SZ * C_SZ)        // 262144

// ======================= scratch (static device globals) =======================
__device__ float g_mean[C_SZ];
__device__ float g_rstd[C_SZ];
__device__ __nv_bfloat16 g_xt[B_SZ * CL];    // RAW x, transposed [B,L,C]
__device__ __nv_bfloat16 g_w[4 * CC];        // Wq',Wk',Wv' (BN-folded), Wp (plain)
__device__ float g_bfold[3 * C_SZ];          // folded biases for q,k,v
__device__ __nv_bfloat16 g_qt[B_SZ * CL];    // q transposed [B,L,C]
__device__ __nv_bfloat16 g_kt[B_SZ * CL];
__device__ __nv_bfloat16 g_v[B_SZ * CL];     // v natural [B,C,L]
__device__ float g_scores[B_SZ * LL];
__device__ __nv_bfloat16 g_at[B_SZ * LL];    // attn probs [B,L,L]
__device__ __nv_bfloat16 g_ht[B_SZ * CL];    // h_ transposed [B,L,C]

// ======================= helpers =======================
__device__ __forceinline__ uint32_t smem_to_u32(const void* p) {
    uint32_t a;
    asm("{ .reg .u64 t; cvta.to.shared.u64 t, %1; cvt.u32.u64 %0, t; }" : "=r"(a) : "l"(p));
    return a;
}
#define SWZ128(off) ((off) ^ (((off) >> 3) & 0x70))

__device__ __forceinline__ void cp16(uint32_t dst, const void* src) {
    asm volatile("cp.async.cg.shared.global [%0], [%1], 16;" :: "r"(dst), "l"(src));
}
__device__ __forceinline__ void cp_commit() {
    asm volatile("cp.async.commit_group;");
}
template <int N>
__device__ __forceinline__ void cp_wait() {
    asm volatile("cp.async.wait_group %0;" :: "n"(N));
}
__device__ __forceinline__ void ldsm4(uint32_t* r, uint32_t addr) {
    asm volatile("ldmatrix.sync.aligned.m8n8.x4.shared.b16 {%0,%1,%2,%3}, [%4];"
                 : "=r"(r[0]), "=r"(r[1]), "=r"(r[2]), "=r"(r[3]) : "r"(addr));
}
__device__ __forceinline__ void mma16816(float* c, const uint32_t* a, uint32_t b0, uint32_t b1) {
    asm volatile(
        "mma.sync.aligned.m16n8k16.row.col.f32.bf16.bf16.f32 "
        "{%0,%1,%2,%3}, {%4,%5,%6,%7}, {%8,%9}, {%0,%1,%2,%3};"
        : "+f"(c[0]), "+f"(c[1]), "+f"(c[2]), "+f"(c[3])
        : "r"(a[0]), "r"(a[1]), "r"(a[2]), "r"(a[3]), "r"(b0), "r"(b1));
}
__device__ __forceinline__ uint32_t pack_bf16(__nv_bfloat16 a, __nv_bfloat16 b) {
    return (uint32_t)__bfloat16_as_ushort(a) | ((uint32_t)__bfloat16_as_ushort(b) << 16);
}

// ======================= BatchNorm stats =======================
__global__ __launch_bounds__(256) void bn_stats(const float* __restrict__ x) {
    const int c = blockIdx.x;
    const float* xc = x + (size_t)c * L_SZ;
    float s = 0.f, ss = 0.f;
    for (int idx = threadIdx.x; idx < B_SZ * L_SZ; idx += 256) {
        int b = idx >> 10, l = idx & (L_SZ - 1);
        float v = xc[(size_t)b * CL + l];
        s += v; ss += v * v;
    }
    __shared__ float shs[256], shq[256];
    shs[threadIdx.x] = s; shq[threadIdx.x] = ss;
    __syncthreads();
    for (int o = 128; o > 0; o >>= 1) {
        if (threadIdx.x < o) { shs[threadIdx.x] += shs[threadIdx.x + o]; shq[threadIdx.x] += shq[threadIdx.x + o]; }
        __syncthreads();
    }
    if (threadIdx.x == 0) {
        const float inv_n = 1.f / (float)(B_SZ * L_SZ);
        float m = shs[0] * inv_n;
        float var = shq[0] * inv_n - m * m;
        g_mean[c] = m;
        g_rstd[c] = rsqrtf(var + BN_EPS);
    }
}

// ======================= x -> RAW transposed bf16 =======================
__global__ __launch_bounds__(256) void transpose_bf16(
    const float* __restrict__ x, __nv_bfloat16* __restrict__ th) {
    __shared__ float tile[32][33];
    const int b = blockIdx.z, c0 = blockIdx.y << 5, l0 = blockIdx.x << 5;
    const int tx = threadIdx.x, ty = threadIdx.y;   // (32, 8)
    const float* xb = x + ((size_t)b * C_SZ + c0) * L_SZ + l0;
#pragma unroll
    for (int r = ty; r < 32; r += 8)
        tile[r][tx] = xb[(size_t)r * L_SZ + tx];
    __syncthreads();
    size_t ob = ((size_t)b * L_SZ + l0) * C_SZ + c0;
#pragma unroll
    for (int r = ty; r < 32; r += 8)
        th[ob + (size_t)r * C_SZ + tx] = __float2bfloat16(tile[tx][r]);
}

// ======================= all 4 weights: (optional BN fold) -> bf16 =======================
__global__ __launch_bounds__(256) void w_fold_bf16(
    const float* __restrict__ Wq, const float* __restrict__ Wk,
    const float* __restrict__ Wv, const float* __restrict__ Wp,
    const float* __restrict__ gamma, __nv_bfloat16* __restrict__ wh) {
    int i = blockIdx.x * 256 + threadIdx.x;
    int which = i >> 18;                 // i / CC
    int j = i & (CC - 1);
    const float* W = which == 0 ? Wq : which == 1 ? Wk : which == 2 ? Wv : Wp;
    float v = W[j];
    if (which < 3) { int c = j & (C_SZ - 1); v *= g_rstd[c] * gamma[c]; }
    wh[i] = __float2bfloat16(v);
}

// folded biases for q,k,v: b'[o] = b[o] + sum_c W[o,c]*(beta[c]-mean[c]*s[c])
__global__ __launch_bounds__(128) void bias_fold_all(
    const float* __restrict__ Wq, const float* __restrict__ bq,
    const float* __restrict__ Wk, const float* __restrict__ bk,
    const float* __restrict__ Wv, const float* __restrict__ bv,
    const float* __restrict__ gamma, const float* __restrict__ beta,
    float* __restrict__ bout) {
    const int o = blockIdx.x, which = blockIdx.y;
    const float* W = which == 0 ? Wq : which == 1 ? Wk : Wv;
    const float* b = which == 0 ? bq : which == 1 ? bk : bv;
    float acc = 0.f;
    for (int c = threadIdx.x; c < C_SZ; c += 128) {
        float s = g_rstd[c] * gamma[c];
        float t = beta[c] - g_mean[c] * s;
        acc += W[o * C_SZ + c] * t;
    }
    __shared__ float sh[128];
    sh[threadIdx.x] = acc;
    __syncthreads();
    for (int o2 = 64; o2 > 0; o2 >>= 1) {
        if (threadIdx.x < o2) sh[threadIdx.x] += sh[threadIdx.x + o2];
        __syncthreads();
    }
    if (threadIdx.x == 0) bout[which * C_SZ + o] = b[o] + sh[0];
}

// ======================= mma.sync bf16 GEMM — CTA tile 256x128, BK=64 =======================
// D[m,n] = sum_k A[m,k]*B[n,k], K-major operands. 8 warps as 4(m) x 2(n),
// warp tile 64x64. Double-buffered cp.async (2 x 48KB stages).
// smem stage: A tile 256x128B at +0, B tile 128x128B at +32768.
// EPI 0: bf16 out, bias per-n; EPI 1: bf16 out, bias per-m; EPI 2: bf16 out, no bias
// EPI 3: fp32 * alpha out;     EPI 4: fp32 + bias per-m + residual out
#define STAGE 49152u
#define SMEM_GEMM_BYTES (2 * STAGE)

template <int EPI>
__global__ void __launch_bounds__(256, 1) mma_gemm(
    const __nv_bfloat16* __restrict__ A, const __nv_bfloat16* __restrict__ B,
    const float* __restrict__ bias, const float* __restrict__ res,
    void* outA,
    int K, int ldA, int ldB, int ldO,
    long sA, long sB, long sO, long sRes, float alpha) {
    extern __shared__ char smem[];
    const uint32_t sb = smem_to_u32(smem);
    const int tid = threadIdx.x, lane = tid & 31, wid = tid >> 5;
    const int bz = blockIdx.z;
    const int m0 = blockIdx.y << 8, n0 = blockIdx.x << 7;

    const char* gA = (const char*)(A + (size_t)bz * sA);
    const char* gB = (const char*)(B + (size_t)bz * sB);
    const size_t ldA2 = (size_t)ldA * 2, ldB2 = (size_t)ldB * 2;

    const int wm = (wid & 3) * 64;     // warp m offset (0..192)
    const int wn = (wid >> 2) * 64;    // warp n offset (0 or 64)

    float acc[4][8][4];
#pragma unroll
    for (int a = 0; a < 4; a++)
#pragma unroll
        for (int b = 0; b < 8; b++)
#pragma unroll
            for (int c = 0; c < 4; c++) acc[a][b][c] = 0.f;

    const int nst = K >> 6;

    // per-thread fixed load coords: i in [0,12), row = i*32 + (tid>>3), ch = tid&7
    const int lrow = tid >> 3, lch = tid & 7;
    auto prefetch = [&](int s) {
        uint32_t st = sb + (uint32_t)(s & 1) * STAGE;
        size_t kb = (size_t)s * 128;   // 64 bf16 = 128B along K
#pragma unroll
        for (int i = 0; i < 8; i++) {  // A rows 0..255
            int row = i * 32 + lrow;
            uint32_t doff = SWZ128((uint32_t)row * 128u + (uint32_t)lch * 16u);
            cp16(st + doff, gA + (size_t)(m0 + row) * ldA2 + kb + (size_t)lch * 16);
        }
#pragma unroll
        for (int i = 0; i < 4; i++) {  // B rows 0..127
            int row = i * 32 + lrow;
            uint32_t doff = SWZ128((uint32_t)row * 128u + (uint32_t)lch * 16u);
            cp16(st + 32768u + doff, gB + (size_t)(n0 + row) * ldB2 + kb + (size_t)lch * 16);
        }
        cp_commit();
    };

    prefetch(0);

    // ldmatrix lane address components (canonical x4 patterns)
    const int a_row  = (lane & 7) + ((lane >> 3) & 1) * 8;
    const int a_koff = (lane >> 4) * 16;                     // bytes
    const int b_row  = (lane & 7) + (lane >> 4) * 8;
    const int b_koff = ((lane >> 3) & 1) * 16;

    for (int s = 0; s < nst; s++) {
        if (s + 1 < nst) { prefetch(s + 1); cp_wait<1>(); }
        else             { cp_wait<0>(); }
        __syncthreads();
        const uint32_t st = sb + (uint32_t)(s & 1) * STAGE;
#pragma unroll
        for (int kk = 0; kk < 4; kk++) {
            uint32_t ah[4][4], bh[4][4];
#pragma unroll
            for (int mi = 0; mi < 4; mi++) {
                uint32_t off = SWZ128((uint32_t)((wm + mi * 16 + a_row) * 128 + kk * 32 + a_koff));
                ldsm4(ah[mi], st + off);
            }
#pragma unroll
            for (int ni = 0; ni < 4; ni++) {
                uint32_t off = SWZ128((uint32_t)((wn + ni * 16 + b_row) * 128 + kk * 32 + b_koff));
                ldsm4(bh[ni], st + 32768u + off);
            }
#pragma unroll
            for (int mi = 0; mi < 4; mi++)
#pragma unroll
                for (int n8 = 0; n8 < 8; n8++) {
                    int ni = n8 >> 1, hf = (n8 & 1) * 2;
                    mma16816(acc[mi][n8], ah[mi], bh[ni][hf], bh[ni][hf + 1]);
                }
        }
        __syncthreads();
    }

    // ---------------- epilogue ----------------
#pragma unroll
    for (int mi = 0; mi < 4; mi++) {
        const int r0 = m0 + wm + mi * 16 + (lane >> 2);
        const int r1 = r0 + 8;
#pragma unroll
        for (int n8 = 0; n8 < 8; n8++) {
            const int col = n0 + wn + n8 * 8 + 2 * (lane & 3);
            float* a4 = acc[mi][n8];
            if (EPI == 3) {
                float* o = (float*)outA + (size_t)bz * sO;
                *(float2*)(o + (size_t)r0 * ldO + col) = make_float2(a4[0] * alpha, a4[1] * alpha);
                *(float2*)(o + (size_t)r1 * ldO + col) = make_float2(a4[2] * alpha, a4[3] * alpha);
            } else if (EPI == 4) {
                float* o = (float*)outA + (size_t)bz * sO;
                const float* rp = res + (size_t)bz * sRes;
                float bi0 = bias[r0], bi1 = bias[r1];
                float2 q0 = *(const float2*)(rp + (size_t)r0 * ldO + col);
                float2 q1 = *(const float2*)(rp + (size_t)r1 * ldO + col);
                *(float2*)(o + (size_t)r0 * ldO + col) = make_float2(a4[0] + bi0 + q0.x, a4[1] + bi0 + q0.y);
                *(float2*)(o + (size_t)r1 * ldO + col) = make_float2(a4[2] + bi1 + q1.x, a4[3] + bi1 + q1.y);
            } else {
                float b00 = 0.f, b01 = 0.f, b10 = 0.f, b11 = 0.f;
                if (EPI == 0) { float bn0 = bias[col], bn1 = bias[col + 1]; b00 = bn0; b01 = bn1; b10 = bn0; b11 = bn1; }
                if (EPI == 1) { float bm0 = bias[r0], bm1 = bias[r1]; b00 = bm0; b01 = bm0; b10 = bm1; b11 = bm1; }
                __nv_bfloat16* oh = (__nv_bfloat16*)outA + (size_t)bz * sO;
                *(uint32_t*)(oh + (size_t)r0 * ldO + col) =
                    pack_bf16(__float2bfloat16(a4[0] + b00), __float2bfloat16(a4[1] + b01));
                *(uint32_t*)(oh + (size_t)r1 * ldO + col) =
                    pack_bf16(__float2bfloat16(a4[2] + b10), __float2bfloat16(a4[3] + b11));
            }
        }
    }
}

// ======================= softmax -> bf16 probs =======================
__global__ __launch_bounds__(256) void softmax_hi(
    const float* __restrict__ sc, __nv_bfloat16* __restrict__ ah) {
    const size_t row = blockIdx.x;
    const float4* p4 = (const float4*)(sc + row * L_SZ);
    const int t = threadIdx.x;
    float4 v = p4[t];
    __shared__ float sh[256];
    float mx = fmaxf(fmaxf(v.x, v.y), fmaxf(v.z, v.w));
    sh[t] = mx; __syncthreads();
    for (int o = 128; o > 0; o >>= 1) {
        if (t < o) sh[t] = fmaxf(sh[t], sh[t + o]);
        __syncthreads();
    }
    mx = sh[0]; __syncthreads();
    v.x = expf(v.x - mx); v.y = expf(v.y - mx);
    v.z = expf(v.z - mx); v.w = expf(v.w - mx);
    sh[t] = v.x + v.y + v.z + v.w; __syncthreads();
    for (int o = 128; o > 0; o >>= 1) {
        if (t < o) sh[t] += sh[t + o];
        __syncthreads();
    }
    float inv = 1.f / sh[0];
    ((uint2*)(ah + row * L_SZ))[t] = make_uint2(
        pack_bf16(__float2bfloat16(v.x * inv), __float2bfloat16(v.y * inv)),
        pack_bf16(__float2bfloat16(v.z * inv), __float2bfloat16(v.w * inv)));
}

// ======================= launch =======================
extern "C" void kernel_launch(void* const* d_in, const int* in_sizes, int n_in,
                              void* d_out, int out_size) {
    const float* x     = (const float*)d_in[0];
    const float* gamma = (const float*)d_in[1];
    const float* beta  = (const float*)d_in[2];
    const float* Wq = (const float*)d_in[3];  const float* bq = (const float*)d_in[4];
    const float* Wk = (const float*)d_in[5];  const float* bk = (const float*)d_in[6];
    const float* Wv = (const float*)d_in[7];  const float* bv = (const float*)d_in[8];
    const float* Wp = (const float*)d_in[9];  const float* bp = (const float*)d_in[10];
    float* out = (float*)d_out;

    __nv_bfloat16 *xt, *w, *qt, *kt, *v, *at, *ht;
    float *scores, *bfold;
    cudaGetSymbolAddress((void**)&xt, g_xt);
    cudaGetSymbolAddress((void**)&w, g_w);
    cudaGetSymbolAddress((void**)&bfold, g_bfold);
    cudaGetSymbolAddress((void**)&qt, g_qt);
    cudaGetSymbolAddress((void**)&kt, g_kt);
    cudaGetSymbolAddress((void**)&v, g_v);
    cudaGetSymbolAddress((void**)&scores, g_scores);
    cudaGetSymbolAddress((void**)&at, g_at);
    cudaGetSymbolAddress((void**)&ht, g_ht);

    cudaFuncSetAttribute(mma_gemm<0>, cudaFuncAttributeMaxDynamicSharedMemorySize, SMEM_GEMM_BYTES);
    cudaFuncSetAttribute(mma_gemm<1>, cudaFuncAttributeMaxDynamicSharedMemorySize, SMEM_GEMM_BYTES);
    cudaFuncSetAttribute(mma_gemm<2>, cudaFuncAttributeMaxDynamicSharedMemorySize, SMEM_GEMM_BYTES);
    cudaFuncSetAttribute(mma_gemm<3>, cudaFuncAttributeMaxDynamicSharedMemorySize, SMEM_GEMM_BYTES);
    cudaFuncSetAttribute(mma_gemm<4>, cudaFuncAttributeMaxDynamicSharedMemorySize, SMEM_GEMM_BYTES);

    // 1. BN stats (feeds the weight/bias folds only)
    bn_stats<<<C_SZ, 256>>>(x);
    // 2. raw x -> transposed bf16 [B,L,C]
    transpose_bf16<<<dim3(32, 16, 16), dim3(32, 8)>>>(x, xt);
    // 3. weights (BN folded into Wq/Wk/Wv) + folded biases
    w_fold_bf16<<<4 * CC / 256, 256>>>(Wq, Wk, Wv, Wp, gamma, w);
    bias_fold_all<<<dim3(C_SZ, 3), 128>>>(Wq, bq, Wk, bk, Wv, bv, gamma, beta, bfold);

    // 4. qt[l,c] = xt[l,:]·Wq'[c,:] + bq'   (M=1024, N=512)
    mma_gemm<0><<<dim3(4, 4, 16), 256, SMEM_GEMM_BYTES>>>(
        xt, w + 0 * CC, bfold + 0 * C_SZ, nullptr, qt,
        C_SZ, C_SZ, C_SZ, C_SZ, CL, 0, CL, 0, 0.f);
    mma_gemm<0><<<dim3(4, 4, 16), 256, SMEM_GEMM_BYTES>>>(
        xt, w + 1 * CC, bfold + 1 * C_SZ, nullptr, kt,
        C_SZ, C_SZ, C_SZ, C_SZ, CL, 0, CL, 0, 0.f);
    // 5. v[c,l] = Wv'[c,:]·xt[l,:] + bv'   (M=512, N=1024)
    mma_gemm<1><<<dim3(8, 2, 16), 256, SMEM_GEMM_BYTES>>>(
        w + 2 * CC, xt, bfold + 2 * C_SZ, nullptr, v,
        C_SZ, C_SZ, C_SZ, L_SZ, 0, CL, CL, 0, 0.f);

    // 6. scores = alpha * qt·kt^T   (M=1024, N=1024)
    const float alpha = 1.f / sqrtf((float)C_SZ);
    mma_gemm<3><<<dim3(8, 4, 16), 256, SMEM_GEMM_BYTES>>>(
        qt, kt, nullptr, nullptr, scores,
        C_SZ, C_SZ, C_SZ, L_SZ, CL, CL, LL, 0, alpha);

    // 7. softmax -> bf16 probs
    softmax_hi<<<B_SZ * L_SZ, 256>>>(scores, at);

    // 8. ht[i,c] = at[i,:]·v[c,:]   (M=1024, N=512, K=1024)
    mma_gemm<2><<<dim3(4, 4, 16), 256, SMEM_GEMM_BYTES>>>(
        at, v, nullptr, nullptr, ht,
        L_SZ, L_SZ, L_SZ, C_SZ, LL, CL, CL, 0, 0.f);

    // 9. out[c,l] = Wp[c,:]·ht[l,:] + bp + x[c,l]   (M=512, N=1024)
    mma_gemm<4><<<dim3(8, 2, 16), 256, SMEM_GEMM_BYTES>>>(
        w + 3 * CC, ht, bp, x, out,
        C_SZ, C_SZ, C_SZ, L_SZ, 0, CL, CL, CL, 0.f);
}